// round 1
// baseline (speedup 1.0000x reference)
#include <cuda_runtime.h>
#include <math.h>

// Problem constants
#define NN   100000
#define EE   1600000
#define FIN  256
#define H1   64
#define H2   128
#define BJ   4096

// ---------------- scratch (device globals; no allocs allowed) ----------------
__device__ float  g_deg[NN];
__device__ float  g_dis[NN];
__device__ float4 g_xws1[NN * (H1 / 4)];   // dis[i] * (x @ W1)      [N,64]
__device__ float4 g_acc1[NN * (H1 / 4)];   // self-loop + edge accum [N,64]
__device__ float4 g_xws2[NN * (H2 / 4)];   // dis[i] * (h1 @ W2)     [N,128]
__device__ float4 g_acc2[NN * (H2 / 4)];   // accum                  [N,128]

// ---------------- degree / normalization ----------------
__global__ void k_deg_init() {
    int i = blockIdx.x * blockDim.x + threadIdx.x;
    if (i < NN) g_deg[i] = 1.0f;            // self-loop weight
}

__global__ void k_deg_edges(const int* __restrict__ dst, const float* __restrict__ ew) {
    int e = blockIdx.x * blockDim.x + threadIdx.x;
    if (e < EE) atomicAdd(&g_deg[dst[e]], ew[e]);
}

__global__ void k_dis() {
    int i = blockIdx.x * blockDim.x + threadIdx.x;
    if (i < NN) g_dis[i] = rsqrtf(g_deg[i]);
}

// ---------------- GEMM1: xws1 = dis[i] * (x @ W1); acc1 = xws1 ----------------
// x: [N,256] f32, W1: [256,64] f32. Block: 32 rows, 128 threads, 4x4 reg tile.
#define G1_SMEM_FLOATS (FIN * H1 + 32 * 260)
__global__ void k_gemm1(const float* __restrict__ x, const float* __restrict__ W1) {
    extern __shared__ float sm[];
    float*  sW  = sm;                 // [256][64] as float4 [256][16]
    float*  sX  = sm + FIN * H1;      // [32][260] padded
    float4* sW4 = (float4*)sW;
    const int t = threadIdx.x;        // 128 threads

    // load W1 (4096 float4)
    const float4* W4 = (const float4*)W1;
#pragma unroll
    for (int i = 0; i < 32; i++) sW4[t + i * 128] = W4[t + i * 128];

    // load x tile: rows rb..rb+31, 2048 float4
    const int rb = blockIdx.x * 32;
    const float4* X4 = (const float4*)(x + (size_t)rb * FIN);
#pragma unroll
    for (int i = 0; i < 16; i++) {
        int idx = t + i * 128;              // 0..2047
        int r = idx >> 6, c = idx & 63;
        float4 v = X4[idx];
        *(float4*)&sX[r * 260 + c * 4] = v;
    }
    __syncthreads();

    const int cg = t & 15;            // column group (4 cols)
    const int r0 = (t >> 4) * 4;      // 4 rows
    float acc[4][4] = {};

#pragma unroll 8
    for (int k = 0; k < FIN; k++) {
        float4 w = sW4[k * 16 + cg];
        float x0 = sX[(r0 + 0) * 260 + k];
        float x1 = sX[(r0 + 1) * 260 + k];
        float x2 = sX[(r0 + 2) * 260 + k];
        float x3 = sX[(r0 + 3) * 260 + k];
        acc[0][0] += x0 * w.x; acc[0][1] += x0 * w.y; acc[0][2] += x0 * w.z; acc[0][3] += x0 * w.w;
        acc[1][0] += x1 * w.x; acc[1][1] += x1 * w.y; acc[1][2] += x1 * w.z; acc[1][3] += x1 * w.w;
        acc[2][0] += x2 * w.x; acc[2][1] += x2 * w.y; acc[2][2] += x2 * w.z; acc[2][3] += x2 * w.w;
        acc[3][0] += x3 * w.x; acc[3][1] += x3 * w.y; acc[3][2] += x3 * w.z; acc[3][3] += x3 * w.w;
    }

#pragma unroll
    for (int i = 0; i < 4; i++) {
        int row = rb + r0 + i;
        float d = g_dis[row];
        float4 v = make_float4(acc[i][0] * d, acc[i][1] * d, acc[i][2] * d, acc[i][3] * d);
        g_xws1[(size_t)row * 16 + cg] = v;
        g_acc1[(size_t)row * 16 + cg] = v;   // self-loop term preloaded
    }
}

// ---------------- scatter1: acc1[dst] += ew * xws1[src]  (64 f32 / edge) ----------------
__global__ void k_scatter1(const int* __restrict__ src, const int* __restrict__ dst,
                           const float* __restrict__ ew) {
    int gid = blockIdx.x * blockDim.x + threadIdx.x;
    int e = gid >> 4;
    int c = gid & 15;
    int lane = threadIdx.x & 31;
    int leader = lane & 16;           // lane 0 or 16 loads for its 16-lane group
    int s = 0, d = 0; float w = 0.f;
    if (c == 0) { s = src[e]; d = dst[e]; w = ew[e]; }
    s = __shfl_sync(0xffffffffu, s, leader);
    d = __shfl_sync(0xffffffffu, d, leader);
    w = __shfl_sync(0xffffffffu, w, leader);
    float4 v = g_xws1[(size_t)s * 16 + c];
    float4* p = &g_acc1[(size_t)d * 16 + c];
    asm volatile("red.global.add.v4.f32 [%0], {%1, %2, %3, %4};"
                 :: "l"(p), "f"(v.x * w), "f"(v.y * w), "f"(v.z * w), "f"(v.w * w)
                 : "memory");
}

// ---------------- GEMM2: h1 = relu(dis*acc1 + b1); xws2 = dis * (h1 @ W2); acc2 = xws2 ----
// W2: [64,128]. Block: 32 rows, 256 threads, 4x4 reg tile.
__global__ void k_gemm2(const float* __restrict__ W2, const float* __restrict__ b1) {
    __shared__ float sW[H1 * H2];      // 32KB, float4 [64][32]
    __shared__ float sH[32 * 68];      // padded h1 tile
    float4* sW4 = (float4*)sW;
    const int t = threadIdx.x;         // 256 threads

    // load W2 (2048 float4)
    const float4* W4 = (const float4*)W2;
#pragma unroll
    for (int i = 0; i < 8; i++) sW4[t + i * 256] = W4[t + i * 256];

    // build h1 tile: relu(dis*acc1 + b1), 512 float4
    const int rb = blockIdx.x * 32;
#pragma unroll
    for (int i = 0; i < 2; i++) {
        int idx = t + i * 256;          // 0..511
        int r = idx >> 4, c = idx & 15;
        float d = g_dis[rb + r];
        float4 a = g_acc1[(size_t)(rb + r) * 16 + c];
        float4 h;
        h.x = fmaxf(fmaf(d, a.x, __ldg(&b1[c * 4 + 0])), 0.f);
        h.y = fmaxf(fmaf(d, a.y, __ldg(&b1[c * 4 + 1])), 0.f);
        h.z = fmaxf(fmaf(d, a.z, __ldg(&b1[c * 4 + 2])), 0.f);
        h.w = fmaxf(fmaf(d, a.w, __ldg(&b1[c * 4 + 3])), 0.f);
        *(float4*)&sH[r * 68 + c * 4] = h;
    }
    __syncthreads();

    const int cg = t & 31;             // 32 column groups
    const int r0 = (t >> 5) * 4;
    float acc[4][4] = {};

#pragma unroll 8
    for (int k = 0; k < H1; k++) {
        float4 w = sW4[k * 32 + cg];
        float x0 = sH[(r0 + 0) * 68 + k];
        float x1 = sH[(r0 + 1) * 68 + k];
        float x2 = sH[(r0 + 2) * 68 + k];
        float x3 = sH[(r0 + 3) * 68 + k];
        acc[0][0] += x0 * w.x; acc[0][1] += x0 * w.y; acc[0][2] += x0 * w.z; acc[0][3] += x0 * w.w;
        acc[1][0] += x1 * w.x; acc[1][1] += x1 * w.y; acc[1][2] += x1 * w.z; acc[1][3] += x1 * w.w;
        acc[2][0] += x2 * w.x; acc[2][1] += x2 * w.y; acc[2][2] += x2 * w.z; acc[2][3] += x2 * w.w;
        acc[3][0] += x3 * w.x; acc[3][1] += x3 * w.y; acc[3][2] += x3 * w.z; acc[3][3] += x3 * w.w;
    }

#pragma unroll
    for (int i = 0; i < 4; i++) {
        int row = rb + r0 + i;
        float d = g_dis[row];
        float4 v = make_float4(acc[i][0] * d, acc[i][1] * d, acc[i][2] * d, acc[i][3] * d);
        g_xws2[(size_t)row * 32 + cg] = v;
        g_acc2[(size_t)row * 32 + cg] = v;
    }
}

// ---------------- scatter2: acc2[dst] += ew * xws2[src]  (128 f32 / edge) ----------------
__global__ void k_scatter2(const int* __restrict__ src, const int* __restrict__ dst,
                           const float* __restrict__ ew) {
    int gid = blockIdx.x * blockDim.x + threadIdx.x;
    int e = gid >> 5;
    int c = gid & 31;
    int s = 0, d = 0; float w = 0.f;
    if (c == 0) { s = src[e]; d = dst[e]; w = ew[e]; }
    s = __shfl_sync(0xffffffffu, s, 0);
    d = __shfl_sync(0xffffffffu, d, 0);
    w = __shfl_sync(0xffffffffu, w, 0);
    float4 v = g_xws2[(size_t)s * 32 + c];
    float4* p = &g_acc2[(size_t)d * 32 + c];
    asm volatile("red.global.add.v4.f32 [%0], {%1, %2, %3, %4};"
                 :: "l"(p), "f"(v.x * w), "f"(v.y * w), "f"(v.z * w), "f"(v.w * w)
                 : "memory");
}

// ---------------- head: out[b] = sigmoid( (dis*acc2[j] + b2) . Wl + bl ) ----------------
__global__ void k_final(const int* __restrict__ join, const float* __restrict__ b2,
                        const float* __restrict__ Wl, const float* __restrict__ bl,
                        float* __restrict__ out) {
    int warp = (blockIdx.x * blockDim.x + threadIdx.x) >> 5;
    int lane = threadIdx.x & 31;
    if (warp >= BJ) return;
    int j = join[warp];
    float d = g_dis[j];
    float4 a = g_acc2[(size_t)j * 32 + lane];
    float4 bb = ((const float4*)b2)[lane];
    float4 wl = ((const float4*)Wl)[lane];
    float s = fmaf(d, a.x, bb.x) * wl.x + fmaf(d, a.y, bb.y) * wl.y +
              fmaf(d, a.z, bb.z) * wl.z + fmaf(d, a.w, bb.w) * wl.w;
#pragma unroll
    for (int o = 16; o > 0; o >>= 1) s += __shfl_down_sync(0xffffffffu, s, o);
    if (lane == 0) {
        float z = s + __ldg(bl);
        out[warp] = 1.0f / (1.0f + expf(-z));
    }
}

// ---------------- launch ----------------
extern "C" void kernel_launch(void* const* d_in, const int* in_sizes, int n_in,
                              void* d_out, int out_size) {
    (void)in_sizes; (void)n_in; (void)out_size;
    const float* x    = (const float*)d_in[0];
    const int*   eidx = (const int*)  d_in[1];
    const int*   join = (const int*)  d_in[2];
    const float* ew   = (const float*)d_in[3];
    const float* W1   = (const float*)d_in[4];
    const float* b1   = (const float*)d_in[5];
    const float* W2   = (const float*)d_in[6];
    const float* b2   = (const float*)d_in[7];
    const float* Wl   = (const float*)d_in[8];
    const float* bl   = (const float*)d_in[9];
    float*       out  = (float*)d_out;

    const int* src = eidx;
    const int* dst = eidx + EE;

    const int g1_smem = G1_SMEM_FLOATS * 4;   // 98816 B
    cudaFuncSetAttribute(k_gemm1, cudaFuncAttributeMaxDynamicSharedMemorySize, g1_smem);

    k_deg_init <<<(NN + 255) / 256, 256>>>();
    k_deg_edges<<<EE / 256, 256>>>(dst, ew);
    k_dis      <<<(NN + 255) / 256, 256>>>();

    k_gemm1    <<<NN / 32, 128, g1_smem>>>(x, W1);
    k_scatter1 <<<(EE * 16) / 256, 256>>>(src, dst, ew);

    k_gemm2    <<<NN / 32, 256>>>(W2, b1);
    k_scatter2 <<<(EE * 32) / 256, 256>>>(src, dst, ew);

    k_final    <<<(BJ * 32) / 256, 256>>>(join, b2, Wl, bl, out);
}

// round 2
// speedup vs baseline: 1.3924x; 1.3924x over previous
#include <cuda_runtime.h>
#include <math.h>

#define NN   100000
#define EE   1600000
#define FIN  256
#define H1   64
#define H2   128
#define BJ   4096

// ---------------- scratch (device globals) ----------------
__device__ float  g_deg[NN];
__device__ float  g_dis[NN];
__device__ int    g_cnt[NN];
__device__ int    g_rowptr[NN + 1];
__device__ int    g_cursor[NN];
__device__ int    g_blksum[128];
__device__ int2   g_edge[EE];              // (src, ew-as-int) sorted by dst
__device__ float4 g_xws1[NN * (H1 / 4)];   // dis[i] * (x @ W1)   [N,64]
__device__ float4 g_h1  [NN * (H1 / 4)];   // relu layer-1 output [N,64]
__device__ float4 g_xws2[NN * (H2 / 4)];   // dis[i] * (h1 @ W2)  [N,128]
__device__ float4 g_h2  [NN * (H2 / 4)];   // layer-2 output+bias [N,128]

// ---------------- init / degree ----------------
__global__ void k_init() {
    int i = blockIdx.x * blockDim.x + threadIdx.x;
    if (i < NN) { g_deg[i] = 1.0f; g_cnt[i] = 0; }
}

__global__ void k_hist(const int* __restrict__ dst, const float* __restrict__ ew) {
    int e = blockIdx.x * blockDim.x + threadIdx.x;
    if (e < EE) {
        int d = dst[e];
        atomicAdd(&g_cnt[d], 1);
        atomicAdd(&g_deg[d], ew[e]);
    }
}

__global__ void k_dis() {
    int i = blockIdx.x * blockDim.x + threadIdx.x;
    if (i < NN) g_dis[i] = rsqrtf(g_deg[i]);
}

// ---------------- 2-level exclusive scan of g_cnt -> g_rowptr ----------------
#define SCAN_BLK 1024
__global__ void k_scan1() {
    __shared__ int sm[SCAN_BLK];
    int t = threadIdx.x;
    int i = blockIdx.x * SCAN_BLK + t;
    int a = (i < NN) ? g_cnt[i] : 0;
    sm[t] = a;
    __syncthreads();
#pragma unroll
    for (int off = 1; off < SCAN_BLK; off <<= 1) {
        int v = (t >= off) ? sm[t - off] : 0;
        __syncthreads();
        sm[t] += v;
        __syncthreads();
    }
    if (i < NN) g_rowptr[i] = sm[t] - a;          // block-local exclusive
    if (t == SCAN_BLK - 1) g_blksum[blockIdx.x] = sm[t];
}

__global__ void k_scan2(int nblk) {
    __shared__ int s[128];
    int t = threadIdx.x;
    if (t < nblk) s[t] = g_blksum[t];
    __syncthreads();
    if (t == 0) {
        int run = 0;
        for (int b = 0; b < nblk; b++) { int v = s[b]; s[b] = run; run += v; }
    }
    __syncthreads();
    if (t < nblk) g_blksum[t] = s[t];
}

__global__ void k_scan_apply() {
    int i = blockIdx.x * blockDim.x + threadIdx.x;
    if (i < NN) {
        int r = g_rowptr[i] + g_blksum[i >> 10];
        g_rowptr[i] = r;
        g_cursor[i] = r;
    }
    if (i == 0) g_rowptr[NN] = EE;
}

__global__ void k_fill(const int* __restrict__ src, const int* __restrict__ dst,
                       const float* __restrict__ ew) {
    int e = blockIdx.x * blockDim.x + threadIdx.x;
    if (e < EE) {
        int d = dst[e];
        int p = atomicAdd(&g_cursor[d], 1);
        g_edge[p] = make_int2(src[e], __float_as_int(ew[e]));
    }
}

// ---------------- GEMM1: xws1 = dis * (x @ W1) ----------------
// W1 (64KB) in smem; x rows streamed via LDG.128 (L1). 128 thr, 32 rows/blk.
__global__ void __launch_bounds__(128, 3) k_gemm1(const float* __restrict__ x,
                                                  const float* __restrict__ W1) {
    extern __shared__ float4 sW4[];            // [256][16] float4
    const int t = threadIdx.x;
    const float4* W4 = (const float4*)W1;
#pragma unroll
    for (int i = 0; i < 32; i++) sW4[t + i * 128] = W4[t + i * 128];
    __syncthreads();

    const int cg = t & 15;
    const int rg = t >> 4;
    const int r0 = blockIdx.x * 32 + rg * 4;
    const float4* X4 = (const float4*)x;       // 64 float4 per row
    float acc[4][4] = {};

#pragma unroll 2
    for (int k4 = 0; k4 < 64; k4++) {
        float4 xv[4];
#pragma unroll
        for (int i = 0; i < 4; i++) xv[i] = __ldg(&X4[(size_t)(r0 + i) * 64 + k4]);
#pragma unroll
        for (int j = 0; j < 4; j++) {
            float4 w = sW4[(k4 * 4 + j) * 16 + cg];
#pragma unroll
            for (int i = 0; i < 4; i++) {
                float xs = (j == 0) ? xv[i].x : (j == 1) ? xv[i].y : (j == 2) ? xv[i].z : xv[i].w;
                acc[i][0] += xs * w.x; acc[i][1] += xs * w.y;
                acc[i][2] += xs * w.z; acc[i][3] += xs * w.w;
            }
        }
    }
#pragma unroll
    for (int i = 0; i < 4; i++) {
        float d = g_dis[r0 + i];
        g_xws1[(size_t)(r0 + i) * 16 + cg] =
            make_float4(acc[i][0] * d, acc[i][1] * d, acc[i][2] * d, acc[i][3] * d);
    }
}

// ---------------- agg1: h1 = relu(dis*(xws1[self] + sum ew*xws1[src]) + b1) ----
// 16 lanes per node (2 nodes / warp).
__global__ void k_agg1(const float* __restrict__ b1) {
    int gt = blockIdx.x * blockDim.x + threadIdx.x;
    int node = gt >> 4;
    int c = gt & 15;
    if (node >= NN) return;
    int beg = g_rowptr[node], end = g_rowptr[node + 1];
    float4 v = g_xws1[(size_t)node * 16 + c];   // self-loop (dis*dis folded at end)
    int i = beg;
    for (; i + 1 < end; i += 2) {
        int2 e0 = __ldg(&g_edge[i]);
        int2 e1 = __ldg(&g_edge[i + 1]);
        float w0 = __int_as_float(e0.y), w1 = __int_as_float(e1.y);
        float4 a = __ldg(&g_xws1[(size_t)e0.x * 16 + c]);
        float4 b = __ldg(&g_xws1[(size_t)e1.x * 16 + c]);
        v.x += w0 * a.x + w1 * b.x;
        v.y += w0 * a.y + w1 * b.y;
        v.z += w0 * a.z + w1 * b.z;
        v.w += w0 * a.w + w1 * b.w;
    }
    if (i < end) {
        int2 e0 = __ldg(&g_edge[i]);
        float w0 = __int_as_float(e0.y);
        float4 a = __ldg(&g_xws1[(size_t)e0.x * 16 + c]);
        v.x += w0 * a.x; v.y += w0 * a.y; v.z += w0 * a.z; v.w += w0 * a.w;
    }
    float d = g_dis[node];
    float4 h;
    h.x = fmaxf(fmaf(d, v.x, __ldg(&b1[c * 4 + 0])), 0.f);
    h.y = fmaxf(fmaf(d, v.y, __ldg(&b1[c * 4 + 1])), 0.f);
    h.z = fmaxf(fmaf(d, v.z, __ldg(&b1[c * 4 + 2])), 0.f);
    h.w = fmaxf(fmaf(d, v.w, __ldg(&b1[c * 4 + 3])), 0.f);
    g_h1[(size_t)node * 16 + c] = h;
}

// ---------------- GEMM2: xws2 = dis * (h1 @ W2) ----------------
// W2 (32KB) static smem; h1 streamed via LDG.128. 256 thr, 32 rows/blk.
__global__ void __launch_bounds__(256, 4) k_gemm2(const float* __restrict__ W2) {
    __shared__ float4 sW4[H1 * H2 / 4];        // [64][32] float4
    const int t = threadIdx.x;
    const float4* W4 = (const float4*)W2;
#pragma unroll
    for (int i = 0; i < 8; i++) sW4[t + i * 256] = W4[t + i * 256];
    __syncthreads();

    const int cg = t & 31;
    const int rg = t >> 5;
    const int r0 = blockIdx.x * 32 + rg * 4;
    float acc[4][4] = {};

#pragma unroll 2
    for (int k4 = 0; k4 < 16; k4++) {
        float4 xv[4];
#pragma unroll
        for (int i = 0; i < 4; i++) xv[i] = g_h1[(size_t)(r0 + i) * 16 + k4];
#pragma unroll
        for (int j = 0; j < 4; j++) {
            float4 w = sW4[(k4 * 4 + j) * 32 + cg];
#pragma unroll
            for (int i = 0; i < 4; i++) {
                float xs = (j == 0) ? xv[i].x : (j == 1) ? xv[i].y : (j == 2) ? xv[i].z : xv[i].w;
                acc[i][0] += xs * w.x; acc[i][1] += xs * w.y;
                acc[i][2] += xs * w.z; acc[i][3] += xs * w.w;
            }
        }
    }
#pragma unroll
    for (int i = 0; i < 4; i++) {
        float d = g_dis[r0 + i];
        g_xws2[(size_t)(r0 + i) * 32 + cg] =
            make_float4(acc[i][0] * d, acc[i][1] * d, acc[i][2] * d, acc[i][3] * d);
    }
}

// ---------------- agg2: h2 = dis*(xws2[self] + sum ew*xws2[src]) + b2 ----------
// 32 lanes per node (1 node / warp).
__global__ void k_agg2(const float* __restrict__ b2) {
    int gt = blockIdx.x * blockDim.x + threadIdx.x;
    int node = gt >> 5;
    int c = gt & 31;
    if (node >= NN) return;
    int beg = g_rowptr[node], end = g_rowptr[node + 1];
    float4 v = g_xws2[(size_t)node * 32 + c];
    int i = beg;
    for (; i + 1 < end; i += 2) {
        int2 e0 = __ldg(&g_edge[i]);
        int2 e1 = __ldg(&g_edge[i + 1]);
        float w0 = __int_as_float(e0.y), w1 = __int_as_float(e1.y);
        float4 a = __ldg(&g_xws2[(size_t)e0.x * 32 + c]);
        float4 b = __ldg(&g_xws2[(size_t)e1.x * 32 + c]);
        v.x += w0 * a.x + w1 * b.x;
        v.y += w0 * a.y + w1 * b.y;
        v.z += w0 * a.z + w1 * b.z;
        v.w += w0 * a.w + w1 * b.w;
    }
    if (i < end) {
        int2 e0 = __ldg(&g_edge[i]);
        float w0 = __int_as_float(e0.y);
        float4 a = __ldg(&g_xws2[(size_t)e0.x * 32 + c]);
        v.x += w0 * a.x; v.y += w0 * a.y; v.z += w0 * a.z; v.w += w0 * a.w;
    }
    float d = g_dis[node];
    float4 bb = ((const float4*)b2)[c];
    g_h2[(size_t)node * 32 + c] =
        make_float4(fmaf(d, v.x, bb.x), fmaf(d, v.y, bb.y),
                    fmaf(d, v.z, bb.z), fmaf(d, v.w, bb.w));
}

// ---------------- head: out = sigmoid(h2[join] . Wl + bl) ----------------
__global__ void k_final(const int* __restrict__ join, const float* __restrict__ Wl,
                        const float* __restrict__ bl, float* __restrict__ out) {
    int warp = (blockIdx.x * blockDim.x + threadIdx.x) >> 5;
    int lane = threadIdx.x & 31;
    if (warp >= BJ) return;
    int j = join[warp];
    float4 a = g_h2[(size_t)j * 32 + lane];
    float4 wl = ((const float4*)Wl)[lane];
    float s = a.x * wl.x + a.y * wl.y + a.z * wl.z + a.w * wl.w;
#pragma unroll
    for (int o = 16; o > 0; o >>= 1) s += __shfl_down_sync(0xffffffffu, s, o);
    if (lane == 0) {
        float z = s + __ldg(bl);
        out[warp] = 1.0f / (1.0f + expf(-z));
    }
}

// ---------------- launch ----------------
extern "C" void kernel_launch(void* const* d_in, const int* in_sizes, int n_in,
                              void* d_out, int out_size) {
    (void)in_sizes; (void)n_in; (void)out_size;
    const float* x    = (const float*)d_in[0];
    const int*   eidx = (const int*)  d_in[1];
    const int*   join = (const int*)  d_in[2];
    const float* ew   = (const float*)d_in[3];
    const float* W1   = (const float*)d_in[4];
    const float* b1   = (const float*)d_in[5];
    const float* W2   = (const float*)d_in[6];
    const float* b2   = (const float*)d_in[7];
    const float* Wl   = (const float*)d_in[8];
    const float* bl   = (const float*)d_in[9];
    float*       out  = (float*)d_out;

    const int* src = eidx;
    const int* dst = eidx + EE;

    const int g1_smem = FIN * H1 * 4;                 // 65536 B
    cudaFuncSetAttribute(k_gemm1, cudaFuncAttributeMaxDynamicSharedMemorySize, g1_smem);

    const int nscan = (NN + SCAN_BLK - 1) / SCAN_BLK; // 98

    k_init       <<<(NN + 255) / 256, 256>>>();
    k_hist       <<<EE / 256, 256>>>(dst, ew);
    k_scan1      <<<nscan, SCAN_BLK>>>();
    k_scan2      <<<1, 128>>>(nscan);
    k_scan_apply <<<(NN + 255) / 256, 256>>>();
    k_dis        <<<(NN + 255) / 256, 256>>>();
    k_fill       <<<EE / 256, 256>>>(src, dst, ew);

    k_gemm1      <<<NN / 32, 128, g1_smem>>>(x, W1);
    k_agg1       <<<(NN * 16 + 255) / 256, 256>>>(b1);
    k_gemm2      <<<NN / 32, 256>>>(W2);
    k_agg2       <<<(NN * 32 + 255) / 256, 256>>>(b2);
    k_final      <<<(BJ * 32) / 256, 256>>>(join, Wl, bl, out);
}

// round 3
// speedup vs baseline: 2.1335x; 1.5323x over previous
#include <cuda_runtime.h>
#include <math.h>

#define NN   100000
#define EE   1600000
#define FIN  256
#define H1   64
#define H2   128
#define BJ   4096

// ---------------- scratch (device globals) ----------------
__device__ float  g_deg[NN];
__device__ float  g_dis[NN];
__device__ int    g_cnt[NN];
__device__ int    g_rowptr[NN + 1];
__device__ int    g_cursor[NN];
__device__ int    g_blksum[128];
__device__ int2   g_edge[EE];              // (src, ew-as-int) grouped by dst
__device__ float4 g_xws1[NN * (H1 / 4)];   // dis[i] * (x @ W1)  [N,64]
__device__ float  g_q[NN];                 // dis[n] * (h1[n] . wf)
__device__ float4 g_wf4[H1 / 4];           // wf = W2 @ Wl  [64]
__device__ float  g_c;                     // b2.Wl + bl

// ---------------- f32x2 helpers (sm_103a packed fp32) ----------------
__device__ __forceinline__ unsigned long long f32x2_fma(unsigned long long a,
                                                        unsigned long long b,
                                                        unsigned long long c) {
    unsigned long long d;
    asm("fma.rn.f32x2 %0, %1, %2, %3;" : "=l"(d) : "l"(a), "l"(b), "l"(c));
    return d;
}
__device__ __forceinline__ unsigned long long f32x2_bcast(float v) {
    unsigned long long d;
    asm("mov.b64 %0, {%1, %2};" : "=l"(d) : "f"(v), "f"(v));
    return d;
}
__device__ __forceinline__ float2 f32x2_unpack(unsigned long long v) {
    float lo, hi;
    asm("mov.b64 {%0, %1}, %2;" : "=f"(lo), "=f"(hi) : "l"(v));
    return make_float2(lo, hi);
}

// ---------------- init / degree ----------------
__global__ void k_init() {
    int i = blockIdx.x * blockDim.x + threadIdx.x;
    if (i < NN) { g_deg[i] = 1.0f; g_cnt[i] = 0; }
}

__global__ void k_hist(const int* __restrict__ dst, const float* __restrict__ ew) {
    int e = blockIdx.x * blockDim.x + threadIdx.x;
    if (e < EE) {
        int d = dst[e];
        atomicAdd(&g_cnt[d], 1);
        atomicAdd(&g_deg[d], ew[e]);
    }
}

// ---------------- 2-level exclusive scan of g_cnt -> g_rowptr ----------------
#define SCAN_BLK 1024
__global__ void k_scan1() {
    __shared__ int sm[SCAN_BLK];
    int t = threadIdx.x;
    int i = blockIdx.x * SCAN_BLK + t;
    int a = (i < NN) ? g_cnt[i] : 0;
    sm[t] = a;
    __syncthreads();
#pragma unroll
    for (int off = 1; off < SCAN_BLK; off <<= 1) {
        int v = (t >= off) ? sm[t - off] : 0;
        __syncthreads();
        sm[t] += v;
        __syncthreads();
    }
    if (i < NN) g_rowptr[i] = sm[t] - a;
    if (t == SCAN_BLK - 1) g_blksum[blockIdx.x] = sm[t];
}

__global__ void k_scan2(int nblk) {
    __shared__ int s[128];
    int t = threadIdx.x;
    if (t < nblk) s[t] = g_blksum[t];
    __syncthreads();
    if (t == 0) {
        int run = 0;
        for (int b = 0; b < nblk; b++) { int v = s[b]; s[b] = run; run += v; }
    }
    __syncthreads();
    if (t < nblk) g_blksum[t] = s[t];
}

// rowptr finalize + cursor init + dis (fused)
__global__ void k_scan_apply() {
    int i = blockIdx.x * blockDim.x + threadIdx.x;
    if (i < NN) {
        int r = g_rowptr[i] + g_blksum[i >> 10];
        g_rowptr[i] = r;
        g_cursor[i] = r;
        g_dis[i] = rsqrtf(g_deg[i]);
    }
    if (i == 0) g_rowptr[NN] = EE;
}

__global__ void k_fill(const int* __restrict__ src, const int* __restrict__ dst,
                       const float* __restrict__ ew) {
    int e = blockIdx.x * blockDim.x + threadIdx.x;
    if (e < EE) {
        int d = dst[e];
        int p = atomicAdd(&g_cursor[d], 1);
        g_edge[p] = make_int2(src[e], __float_as_int(ew[e]));
    }
}

// ---------------- wf = W2 @ Wl, c = b2.Wl + bl ----------------
__global__ void k_wf(const float* __restrict__ W2, const float* __restrict__ b2,
                     const float* __restrict__ Wl, const float* __restrict__ bl) {
    __shared__ float sWl[H2];
    __shared__ float red[H2];
    int t = threadIdx.x;   // 128
    sWl[t] = Wl[t];
    __syncthreads();
    if (t < H1) {
        float s = 0.f;
#pragma unroll 8
        for (int m = 0; m < H2; m++) s += W2[t * H2 + m] * sWl[m];
        ((float*)g_wf4)[t] = s;
    }
    red[t] = b2[t] * sWl[t];
    __syncthreads();
    if (t == 0) {
        float s = 0.f;
        for (int m = 0; m < H2; m++) s += red[m];
        g_c = s + bl[0];
    }
}

// ---------------- GEMM1: xws1 = dis * (x @ W1), FFMA2 path ----------------
// W1 (64KB) in smem (read as packed u64 pairs); x streamed via LDG.128.
__global__ void __launch_bounds__(128, 3) k_gemm1(const float* __restrict__ x,
                                                  const float* __restrict__ W1) {
    extern __shared__ float4 sW4[];            // [256][16] float4
    const int t = threadIdx.x;
    const float4* W4 = (const float4*)W1;
#pragma unroll
    for (int i = 0; i < 32; i++) sW4[t + i * 128] = W4[t + i * 128];
    __syncthreads();

    const ulonglong2* sWp = (const ulonglong2*)sW4;   // .x=(w0,w1) .y=(w2,w3)
    const int cg = t & 15;
    const int rg = t >> 4;
    const int r0 = blockIdx.x * 32 + rg * 4;
    const float4* X4 = (const float4*)x;

    unsigned long long acc[4][2];
#pragma unroll
    for (int i = 0; i < 4; i++) { acc[i][0] = 0ull; acc[i][1] = 0ull; }

#pragma unroll 2
    for (int k4 = 0; k4 < 64; k4++) {
        float4 xv[4];
#pragma unroll
        for (int i = 0; i < 4; i++) xv[i] = __ldg(&X4[(size_t)(r0 + i) * 64 + k4]);
#pragma unroll
        for (int j = 0; j < 4; j++) {
            ulonglong2 w = sWp[(k4 * 4 + j) * 16 + cg];
#pragma unroll
            for (int i = 0; i < 4; i++) {
                float xs = (j == 0) ? xv[i].x : (j == 1) ? xv[i].y
                         : (j == 2) ? xv[i].z : xv[i].w;
                unsigned long long xp = f32x2_bcast(xs);
                acc[i][0] = f32x2_fma(xp, w.x, acc[i][0]);
                acc[i][1] = f32x2_fma(xp, w.y, acc[i][1]);
            }
        }
    }
#pragma unroll
    for (int i = 0; i < 4; i++) {
        float d = g_dis[r0 + i];
        float2 a01 = f32x2_unpack(acc[i][0]);
        float2 a23 = f32x2_unpack(acc[i][1]);
        g_xws1[(size_t)(r0 + i) * 16 + cg] =
            make_float4(a01.x * d, a01.y * d, a23.x * d, a23.y * d);
    }
}

// -------- agg1q: v = xws1[n] + sum ew*xws1[src]; h1 = relu(dis*v + b1);
//          q[n] = dis[n] * (h1 . wf).  16 lanes/node. --------
__global__ void k_agg1q(const float* __restrict__ b1) {
    int gt = blockIdx.x * blockDim.x + threadIdx.x;
    int node = gt >> 4;
    int c = gt & 15;
    if (node >= NN) return;
    int beg = g_rowptr[node], end = g_rowptr[node + 1];
    float4 v = g_xws1[(size_t)node * 16 + c];
    int i = beg;
    for (; i + 1 < end; i += 2) {
        int2 e0 = __ldg(&g_edge[i]);
        int2 e1 = __ldg(&g_edge[i + 1]);
        float w0 = __int_as_float(e0.y), w1 = __int_as_float(e1.y);
        float4 a = __ldg(&g_xws1[(size_t)e0.x * 16 + c]);
        float4 b = __ldg(&g_xws1[(size_t)e1.x * 16 + c]);
        v.x += w0 * a.x + w1 * b.x;
        v.y += w0 * a.y + w1 * b.y;
        v.z += w0 * a.z + w1 * b.z;
        v.w += w0 * a.w + w1 * b.w;
    }
    if (i < end) {
        int2 e0 = __ldg(&g_edge[i]);
        float w0 = __int_as_float(e0.y);
        float4 a = __ldg(&g_xws1[(size_t)e0.x * 16 + c]);
        v.x += w0 * a.x; v.y += w0 * a.y; v.z += w0 * a.z; v.w += w0 * a.w;
    }
    float d = g_dis[node];
    float4 bb = __ldg(&((const float4*)b1)[c]);
    float hx = fmaxf(fmaf(d, v.x, bb.x), 0.f);
    float hy = fmaxf(fmaf(d, v.y, bb.y), 0.f);
    float hz = fmaxf(fmaf(d, v.z, bb.z), 0.f);
    float hw = fmaxf(fmaf(d, v.w, bb.w), 0.f);
    float4 wf = g_wf4[c];
    float s = hx * wf.x + hy * wf.y + hz * wf.z + hw * wf.w;
#pragma unroll
    for (int o = 8; o > 0; o >>= 1) s += __shfl_down_sync(0xffffffffu, s, o);
    if (c == 0) g_q[node] = d * s;
}

// ---------------- head: out[b] = sigmoid(dis[j]*(q[j] + sum ew*q[src]) + c) ----
__global__ void k_head(const int* __restrict__ join, float* __restrict__ out) {
    int warp = (blockIdx.x * blockDim.x + threadIdx.x) >> 5;
    int lane = threadIdx.x & 31;
    if (warp >= BJ) return;
    int j = join[warp];
    int beg = g_rowptr[j], end = g_rowptr[j + 1];
    float acc = 0.f;
    for (int i = beg + lane; i < end; i += 32) {
        int2 e = __ldg(&g_edge[i]);
        acc += __int_as_float(e.y) * __ldg(&g_q[e.x]);
    }
#pragma unroll
    for (int o = 16; o > 0; o >>= 1) acc += __shfl_down_sync(0xffffffffu, acc, o);
    if (lane == 0) {
        float z = g_dis[j] * (g_q[j] + acc) + g_c;
        out[warp] = 1.0f / (1.0f + expf(-z));
    }
}

// ---------------- launch ----------------
extern "C" void kernel_launch(void* const* d_in, const int* in_sizes, int n_in,
                              void* d_out, int out_size) {
    (void)in_sizes; (void)n_in; (void)out_size;
    const float* x    = (const float*)d_in[0];
    const int*   eidx = (const int*)  d_in[1];
    const int*   join = (const int*)  d_in[2];
    const float* ew   = (const float*)d_in[3];
    const float* W1   = (const float*)d_in[4];
    const float* b1   = (const float*)d_in[5];
    const float* W2   = (const float*)d_in[6];
    const float* b2   = (const float*)d_in[7];
    const float* Wl   = (const float*)d_in[8];
    const float* bl   = (const float*)d_in[9];
    float*       out  = (float*)d_out;

    const int* src = eidx;
    const int* dst = eidx + EE;

    const int g1_smem = FIN * H1 * 4;                 // 65536 B
    cudaFuncSetAttribute(k_gemm1, cudaFuncAttributeMaxDynamicSharedMemorySize, g1_smem);

    const int nscan = (NN + SCAN_BLK - 1) / SCAN_BLK; // 98

    // launch order puts k_gemm1 at index 5 so ncu (-s 5 -c 1) profiles it
    k_init       <<<(NN + 255) / 256, 256>>>();                    // 0
    k_hist       <<<EE / 256, 256>>>(dst, ew);                     // 1
    k_scan1      <<<nscan, SCAN_BLK>>>();                          // 2
    k_scan2      <<<1, 128>>>(nscan);                              // 3
    k_scan_apply <<<(NN + 255) / 256, 256>>>();                    // 4
    k_gemm1      <<<NN / 32, 128, g1_smem>>>(x, W1);               // 5  <- profiled
    k_fill       <<<EE / 256, 256>>>(src, dst, ew);                // 6
    k_wf         <<<1, 128>>>(W2, b2, Wl, bl);                     // 7
    k_agg1q      <<<(NN * 16 + 255) / 256, 256>>>(b1);             // 8
    k_head       <<<(BJ * 32) / 256, 256>>>(join, out);            // 9
}

// round 4
// speedup vs baseline: 2.2198x; 1.0405x over previous
#include <cuda_runtime.h>
#include <math.h>

#define NN   100000
#define EE   1600000
#define FIN  256
#define H1   64
#define H2   128
#define BJ   4096

// ---------------- scratch (device globals) ----------------
__device__ float  g_deg[NN];
__device__ float  g_dis[NN];
__device__ int    g_cnt[NN];
__device__ int    g_rowptr[NN + 1];
__device__ int    g_cursor[NN];
__device__ int    g_blksum[128];
__device__ int2   g_edge[EE];              // (src, ew*dis[src]) grouped by dst
__device__ float4 g_xws1[NN * (H1 / 4)];   // raw x @ W1   [N,64]
__device__ float  g_p[NN];                 // h1[n] . wf
__device__ float4 g_wf4[H1 / 4];           // wf = W2 @ Wl  [64]
__device__ float  g_c;                     // b2.Wl + bl

// ---------------- f32x2 helpers (sm_103a packed fp32) ----------------
__device__ __forceinline__ unsigned long long f32x2_fma(unsigned long long a,
                                                        unsigned long long b,
                                                        unsigned long long c) {
    unsigned long long d;
    asm("fma.rn.f32x2 %0, %1, %2, %3;" : "=l"(d) : "l"(a), "l"(b), "l"(c));
    return d;
}
__device__ __forceinline__ unsigned long long f32x2_bcast(float v) {
    unsigned long long d;
    asm("mov.b64 %0, {%1, %2};" : "=l"(d) : "f"(v), "f"(v));
    return d;
}
__device__ __forceinline__ float2 f32x2_unpack(unsigned long long v) {
    float lo, hi;
    asm("mov.b64 {%0, %1}, %2;" : "=f"(lo), "=f"(hi) : "l"(v));
    return make_float2(lo, hi);
}

// ---------------- init / degree ----------------
__global__ void k_init() {
    int i = blockIdx.x * blockDim.x + threadIdx.x;
    if (i < NN) { g_deg[i] = 1.0f; g_cnt[i] = 0; }
}

__global__ void k_hist(const int* __restrict__ dst, const float* __restrict__ ew) {
    int e = blockIdx.x * blockDim.x + threadIdx.x;
    if (e < EE) {
        int d = dst[e];
        atomicAdd(&g_cnt[d], 1);
        atomicAdd(&g_deg[d], ew[e]);
    }
}

// ---------------- 2-level exclusive scan of g_cnt -> g_rowptr ----------------
#define SCAN_BLK 1024
__global__ void k_scan1() {
    __shared__ int sm[SCAN_BLK];
    int t = threadIdx.x;
    int i = blockIdx.x * SCAN_BLK + t;
    int a = (i < NN) ? g_cnt[i] : 0;
    sm[t] = a;
    __syncthreads();
#pragma unroll
    for (int off = 1; off < SCAN_BLK; off <<= 1) {
        int v = (t >= off) ? sm[t - off] : 0;
        __syncthreads();
        sm[t] += v;
        __syncthreads();
    }
    if (i < NN) g_rowptr[i] = sm[t] - a;
    if (t == SCAN_BLK - 1) g_blksum[blockIdx.x] = sm[t];
}

__global__ void k_scan2(int nblk) {
    __shared__ int s[128];
    int t = threadIdx.x;
    if (t < nblk) s[t] = g_blksum[t];
    __syncthreads();
    if (t == 0) {
        int run = 0;
        for (int b = 0; b < nblk; b++) { int v = s[b]; s[b] = run; run += v; }
    }
    __syncthreads();
    if (t < nblk) g_blksum[t] = s[t];
}

// rowptr finalize + cursor init + dis (fused)
__global__ void k_scan_apply() {
    int i = blockIdx.x * blockDim.x + threadIdx.x;
    if (i < NN) {
        int r = g_rowptr[i] + g_blksum[i >> 10];
        g_rowptr[i] = r;
        g_cursor[i] = r;
        g_dis[i] = rsqrtf(g_deg[i]);
    }
    if (i == 0) g_rowptr[NN] = EE;
}

// fill edges grouped by dst, folding dis[src] into the weight
__global__ void k_fill(const int* __restrict__ src, const int* __restrict__ dst,
                       const float* __restrict__ ew) {
    int e = blockIdx.x * blockDim.x + threadIdx.x;
    if (e < EE) {
        int d = dst[e];
        int s = src[e];
        int p = atomicAdd(&g_cursor[d], 1);
        g_edge[p] = make_int2(s, __float_as_int(ew[e] * g_dis[s]));
    }
}

// ---------------- wf = W2 @ Wl, c = b2.Wl + bl ----------------
__global__ void k_wf(const float* __restrict__ W2, const float* __restrict__ b2,
                     const float* __restrict__ Wl, const float* __restrict__ bl) {
    __shared__ float sWl[H2];
    __shared__ float red[H2];
    int t = threadIdx.x;   // 128
    sWl[t] = Wl[t];
    __syncthreads();
    if (t < H1) {
        float s = 0.f;
#pragma unroll 8
        for (int m = 0; m < H2; m++) s += W2[t * H2 + m] * sWl[m];
        ((float*)g_wf4)[t] = s;
    }
    red[t] = b2[t] * sWl[t];
    __syncthreads();
    if (t == 0) {
        float s = 0.f;
        for (int m = 0; m < H2; m++) s += red[m];
        g_c = s + bl[0];
    }
}

// ---------------- GEMM1: xws1 = x @ W1 (raw), FFMA2 path ----------------
__global__ void __launch_bounds__(128, 3) k_gemm1(const float* __restrict__ x,
                                                  const float* __restrict__ W1) {
    extern __shared__ float4 sW4[];            // [256][16] float4
    const int t = threadIdx.x;
    const float4* W4 = (const float4*)W1;
#pragma unroll
    for (int i = 0; i < 32; i++) sW4[t + i * 128] = W4[t + i * 128];
    __syncthreads();

    const ulonglong2* sWp = (const ulonglong2*)sW4;
    const int cg = t & 15;
    const int rg = t >> 4;
    const int r0 = blockIdx.x * 32 + rg * 4;
    const float4* X4 = (const float4*)x;

    unsigned long long acc[4][2];
#pragma unroll
    for (int i = 0; i < 4; i++) { acc[i][0] = 0ull; acc[i][1] = 0ull; }

#pragma unroll 2
    for (int k4 = 0; k4 < 64; k4++) {
        float4 xv[4];
#pragma unroll
        for (int i = 0; i < 4; i++) xv[i] = __ldg(&X4[(size_t)(r0 + i) * 64 + k4]);
#pragma unroll
        for (int j = 0; j < 4; j++) {
            ulonglong2 w = sWp[(k4 * 4 + j) * 16 + cg];
#pragma unroll
            for (int i = 0; i < 4; i++) {
                float xs = (j == 0) ? xv[i].x : (j == 1) ? xv[i].y
                         : (j == 2) ? xv[i].z : xv[i].w;
                unsigned long long xp = f32x2_bcast(xs);
                acc[i][0] = f32x2_fma(xp, w.x, acc[i][0]);
                acc[i][1] = f32x2_fma(xp, w.y, acc[i][1]);
            }
        }
    }
#pragma unroll
    for (int i = 0; i < 4; i++) {
        float2 a01 = f32x2_unpack(acc[i][0]);
        float2 a23 = f32x2_unpack(acc[i][1]);
        g_xws1[(size_t)(r0 + i) * 16 + cg] = make_float4(a01.x, a01.y, a23.x, a23.y);
    }
}

// -------- agg1q: v = sum ew'*xw[src]; h1 = relu(dis*(v + dis*xw[n]) + b1);
//          p[n] = h1 . wf.  16 lanes/node. --------
__global__ void k_agg1q(const float* __restrict__ b1) {
    int gt = blockIdx.x * blockDim.x + threadIdx.x;
    int node = gt >> 4;
    int c = gt & 15;
    if (node >= NN) return;
    int beg = g_rowptr[node], end = g_rowptr[node + 1];
    float4 v = make_float4(0.f, 0.f, 0.f, 0.f);
    int i = beg;
    for (; i + 1 < end; i += 2) {
        int2 e0 = __ldg(&g_edge[i]);
        int2 e1 = __ldg(&g_edge[i + 1]);
        float w0 = __int_as_float(e0.y), w1 = __int_as_float(e1.y);
        float4 a = __ldg(&g_xws1[(size_t)e0.x * 16 + c]);
        float4 b = __ldg(&g_xws1[(size_t)e1.x * 16 + c]);
        v.x += w0 * a.x + w1 * b.x;
        v.y += w0 * a.y + w1 * b.y;
        v.z += w0 * a.z + w1 * b.z;
        v.w += w0 * a.w + w1 * b.w;
    }
    if (i < end) {
        int2 e0 = __ldg(&g_edge[i]);
        float w0 = __int_as_float(e0.y);
        float4 a = __ldg(&g_xws1[(size_t)e0.x * 16 + c]);
        v.x += w0 * a.x; v.y += w0 * a.y; v.z += w0 * a.z; v.w += w0 * a.w;
    }
    float d = g_dis[node];
    float4 sv = g_xws1[(size_t)node * 16 + c];
    float4 bb = __ldg(&((const float4*)b1)[c]);
    float hx = fmaxf(fmaf(d, fmaf(d, sv.x, v.x), bb.x), 0.f);
    float hy = fmaxf(fmaf(d, fmaf(d, sv.y, v.y), bb.y), 0.f);
    float hz = fmaxf(fmaf(d, fmaf(d, sv.z, v.z), bb.z), 0.f);
    float hw = fmaxf(fmaf(d, fmaf(d, sv.w, v.w), bb.w), 0.f);
    float4 wf = g_wf4[c];
    float s = hx * wf.x + hy * wf.y + hz * wf.z + hw * wf.w;
#pragma unroll
    for (int o = 8; o > 0; o >>= 1) s += __shfl_down_sync(0xffffffffu, s, o);
    if (c == 0) g_p[node] = s;
}

// ---------------- head: out[b] = sigmoid(dis[j]*(sum ew'*p[src] + dis[j]*p[j]) + c) ----
__global__ void k_head(const int* __restrict__ join, float* __restrict__ out) {
    int warp = (blockIdx.x * blockDim.x + threadIdx.x) >> 5;
    int lane = threadIdx.x & 31;
    if (warp >= BJ) return;
    int j = join[warp];
    int beg = g_rowptr[j], end = g_rowptr[j + 1];
    float acc = 0.f;
    for (int i = beg + lane; i < end; i += 32) {
        int2 e = __ldg(&g_edge[i]);
        acc += __int_as_float(e.y) * __ldg(&g_p[e.x]);
    }
#pragma unroll
    for (int o = 16; o > 0; o >>= 1) acc += __shfl_down_sync(0xffffffffu, acc, o);
    if (lane == 0) {
        float d = g_dis[j];
        float z = d * fmaf(d, g_p[j], acc) + g_c;
        out[warp] = 1.0f / (1.0f + expf(-z));
    }
}

// ---------------- launch ----------------
extern "C" void kernel_launch(void* const* d_in, const int* in_sizes, int n_in,
                              void* d_out, int out_size) {
    (void)in_sizes; (void)n_in; (void)out_size;
    const float* x    = (const float*)d_in[0];
    const int*   eidx = (const int*)  d_in[1];
    const int*   join = (const int*)  d_in[2];
    const float* ew   = (const float*)d_in[3];
    const float* W1   = (const float*)d_in[4];
    const float* b1   = (const float*)d_in[5];
    const float* W2   = (const float*)d_in[6];
    const float* b2   = (const float*)d_in[7];
    const float* Wl   = (const float*)d_in[8];
    const float* bl   = (const float*)d_in[9];
    float*       out  = (float*)d_out;

    const int* src = eidx;
    const int* dst = eidx + EE;

    // one-time infra (host objects; created during the eager correctness call)
    static cudaStream_t sA = 0;
    static cudaEvent_t evRoot = 0, evA = 0;
    static bool inited = false;
    if (!inited) {
        cudaStreamCreateWithFlags(&sA, cudaStreamNonBlocking);
        cudaEventCreateWithFlags(&evRoot, cudaEventDisableTiming);
        cudaEventCreateWithFlags(&evA, cudaEventDisableTiming);
        inited = true;
    }

    const int g1_smem = FIN * H1 * 4;                 // 65536 B
    static bool attrSet = false;
    if (!attrSet) {
        cudaFuncSetAttribute(k_gemm1, cudaFuncAttributeMaxDynamicSharedMemorySize, g1_smem);
        attrSet = true;
    }

    const int nscan = (NN + SCAN_BLK - 1) / SCAN_BLK; // 98

    // fork: side stream A runs gemm1 + wf concurrently with the CSR chain (stream 0)
    cudaEventRecord(evRoot, 0);
    cudaStreamWaitEvent(sA, evRoot, 0);

    k_init       <<<(NN + 255) / 256, 256>>>();                        // #0 (B)
    k_hist       <<<EE / 256, 256>>>(dst, ew);                         // #1 (B)
    k_scan1      <<<nscan, SCAN_BLK>>>();                              // #2 (B)
    k_gemm1      <<<NN / 32, 128, g1_smem, sA>>>(x, W1);               // #3 (A) <- profiled
    k_wf         <<<1, 128, 0, sA>>>(W2, b2, Wl, bl);                  // #4 (A)
    k_scan2      <<<1, 128>>>(nscan);                                  // #5 (B)
    k_scan_apply <<<(NN + 255) / 256, 256>>>();                        // #6 (B)
    k_fill       <<<EE / 256, 256>>>(src, dst, ew);                    // #7 (B)

    cudaEventRecord(evA, sA);
    cudaStreamWaitEvent(0, evA, 0);                                    // join A -> B

    k_agg1q      <<<(NN * 16 + 255) / 256, 256>>>(b1);                 // #8
    k_head       <<<(BJ * 32) / 256, 256>>>(join, out);                // #9
}

// round 5
// speedup vs baseline: 2.6922x; 1.2128x over previous
#include <cuda_runtime.h>
#include <math.h>

#define NN   100000
#define EE   1600000
#define FIN  256
#define H1   64
#define H2   128
#define BJ   4096

// ---------------- scratch (device globals) ----------------
__device__ float  g_deg[NN];
__device__ float  g_dis[NN];
__device__ int    g_cnt[NN];
__device__ int    g_rowptr[NN + 1];
__device__ int    g_cursor[NN];
__device__ int    g_blksum[128];
__device__ int2   g_edge[EE];              // (src, ew*dis[src]) grouped by dst
__device__ float4 g_xws1[NN * (H1 / 4)];   // raw x @ W1   [N,64]
__device__ float  g_p[NN];                 // h1[n] . wf
__device__ float4 g_wf4[H1 / 4];           // wf = W2 @ Wl  [64]
__device__ float  g_c;                     // b2.Wl + bl

// ---------------- f32x2 helpers (sm_103a packed fp32) ----------------
__device__ __forceinline__ unsigned long long f32x2_fma(unsigned long long a,
                                                        unsigned long long b,
                                                        unsigned long long c) {
    unsigned long long d;
    asm("fma.rn.f32x2 %0, %1, %2, %3;" : "=l"(d) : "l"(a), "l"(b), "l"(c));
    return d;
}
__device__ __forceinline__ unsigned long long f32x2_bcast(float v) {
    unsigned long long d;
    asm("mov.b64 %0, {%1, %2};" : "=l"(d) : "f"(v), "f"(v));
    return d;
}
__device__ __forceinline__ float2 f32x2_unpack(unsigned long long v) {
    float lo, hi;
    asm("mov.b64 {%0, %1}, %2;" : "=f"(lo), "=f"(hi) : "l"(v));
    return make_float2(lo, hi);
}

// ---------------- init / degree ----------------
__global__ void k_init() {
    int i = blockIdx.x * blockDim.x + threadIdx.x;
    if (i < NN) { g_deg[i] = 1.0f; g_cnt[i] = 0; }
}

__global__ void k_hist(const int* __restrict__ dst, const float* __restrict__ ew) {
    int e = blockIdx.x * blockDim.x + threadIdx.x;
    if (e < EE) {
        int d = dst[e];
        atomicAdd(&g_cnt[d], 1);
        atomicAdd(&g_deg[d], ew[e]);
    }
}

// ---------------- 2-level exclusive scan of g_cnt -> g_rowptr ----------------
#define SCAN_BLK 1024
__global__ void k_scan1() {
    __shared__ int sm[SCAN_BLK];
    int t = threadIdx.x;
    int i = blockIdx.x * SCAN_BLK + t;
    int a = (i < NN) ? g_cnt[i] : 0;
    sm[t] = a;
    __syncthreads();
#pragma unroll
    for (int off = 1; off < SCAN_BLK; off <<= 1) {
        int v = (t >= off) ? sm[t - off] : 0;
        __syncthreads();
        sm[t] += v;
        __syncthreads();
    }
    if (i < NN) g_rowptr[i] = sm[t] - a;
    if (t == SCAN_BLK - 1) g_blksum[blockIdx.x] = sm[t];
}

__global__ void k_scan2(int nblk) {
    __shared__ int s[128];
    int t = threadIdx.x;
    if (t < nblk) s[t] = g_blksum[t];
    __syncthreads();
    if (t == 0) {
        int run = 0;
        for (int b = 0; b < nblk; b++) { int v = s[b]; s[b] = run; run += v; }
    }
    __syncthreads();
    if (t < nblk) g_blksum[t] = s[t];
}

// rowptr finalize + cursor init + dis (fused)
__global__ void k_scan_apply() {
    int i = blockIdx.x * blockDim.x + threadIdx.x;
    if (i < NN) {
        int r = g_rowptr[i] + g_blksum[i >> 10];
        g_rowptr[i] = r;
        g_cursor[i] = r;
        g_dis[i] = rsqrtf(g_deg[i]);
    }
    if (i == 0) g_rowptr[NN] = EE;
}

// fill edges grouped by dst, folding dis[src] into the weight
__global__ void k_fill(const int* __restrict__ src, const int* __restrict__ dst,
                       const float* __restrict__ ew) {
    int e = blockIdx.x * blockDim.x + threadIdx.x;
    if (e < EE) {
        int d = dst[e];
        int s = src[e];
        int p = atomicAdd(&g_cursor[d], 1);
        g_edge[p] = make_int2(s, __float_as_int(ew[e] * g_dis[s]));
    }
}

// ---------------- wf = W2 @ Wl, c = b2.Wl + bl ----------------
__global__ void k_wf(const float* __restrict__ W2, const float* __restrict__ b2,
                     const float* __restrict__ Wl, const float* __restrict__ bl) {
    __shared__ float sWl[H2];
    __shared__ float red[H2];
    int t = threadIdx.x;   // 128
    sWl[t] = Wl[t];
    __syncthreads();
    if (t < H1) {
        float s = 0.f;
#pragma unroll 8
        for (int m = 0; m < H2; m++) s += W2[t * H2 + m] * sWl[m];
        ((float*)g_wf4)[t] = s;
    }
    red[t] = b2[t] * sWl[t];
    __syncthreads();
    if (t == 0) {
        float s = 0.f;
        for (int m = 0; m < H2; m++) s += red[m];
        g_c = s + bl[0];
    }
}

// ---------------- GEMM1: xws1 = x @ W1 (raw) ----------------
// W (64KB) + x tile (32x65 float4, 33.3KB) both in smem; FFMA2 compute.
// 128 thr, 32 rows x 64 cols per block, 4x4 thread tile. 2 CTAs/SM.
#define G1_SMEM_F4 (FIN * 16 + 32 * 65)
__global__ void __launch_bounds__(128, 2) k_gemm1(const float* __restrict__ x,
                                                  const float* __restrict__ W1) {
    extern __shared__ float4 sm4[];
    float4* sW4 = sm4;                      // [256*16]
    float4* sX4 = sm4 + FIN * 16;           // [32][65] padded
    const int t = threadIdx.x;

    const float4* W4 = (const float4*)W1;
#pragma unroll
    for (int i = 0; i < 32; i++) sW4[t + i * 128] = W4[t + i * 128];

    const int rb = blockIdx.x * 32;
    const float4* X4 = (const float4*)(x + (size_t)rb * FIN);
#pragma unroll
    for (int i = 0; i < 16; i++) {
        int idx = t + i * 128;              // 0..2047
        int r = idx >> 6, kq = idx & 63;    // coalesced: lanes = consecutive kq
        sX4[r * 65 + kq] = X4[idx];
    }
    __syncthreads();

    const ulonglong2* sWp = (const ulonglong2*)sW4;  // per W k-row: 8 u64 pairs
    const int cg = t & 15;                  // 4 cols
    const int rg = t >> 4;                  // 4 rows
    const int r0 = rg * 4;

    unsigned long long acc[4][2];
#pragma unroll
    for (int i = 0; i < 4; i++) { acc[i][0] = 0ull; acc[i][1] = 0ull; }

#pragma unroll 2
    for (int k4 = 0; k4 < 64; k4++) {
        float4 xv[4];
#pragma unroll
        for (int i = 0; i < 4; i++) xv[i] = sX4[(r0 + i) * 65 + k4];
#pragma unroll
        for (int j = 0; j < 4; j++) {
            ulonglong2 w = sWp[(k4 * 4 + j) * 16 + cg];
#pragma unroll
            for (int i = 0; i < 4; i++) {
                float xs = (j == 0) ? xv[i].x : (j == 1) ? xv[i].y
                         : (j == 2) ? xv[i].z : xv[i].w;
                unsigned long long xp = f32x2_bcast(xs);
                acc[i][0] = f32x2_fma(xp, w.x, acc[i][0]);
                acc[i][1] = f32x2_fma(xp, w.y, acc[i][1]);
            }
        }
    }
#pragma unroll
    for (int i = 0; i < 4; i++) {
        float2 a01 = f32x2_unpack(acc[i][0]);
        float2 a23 = f32x2_unpack(acc[i][1]);
        g_xws1[(size_t)(rb + r0 + i) * 16 + cg] = make_float4(a01.x, a01.y, a23.x, a23.y);
    }
}

// -------- agg1q: v = sum ew'*xw[src]; h1 = relu(dis*(v + dis*xw[n]) + b1);
//          p[n] = h1 . wf.  16 lanes/node. --------
__global__ void k_agg1q(const float* __restrict__ b1) {
    int gt = blockIdx.x * blockDim.x + threadIdx.x;
    int node = gt >> 4;
    int c = gt & 15;
    if (node >= NN) return;
    int beg = g_rowptr[node], end = g_rowptr[node + 1];
    float4 v = make_float4(0.f, 0.f, 0.f, 0.f);
    int i = beg;
    for (; i + 1 < end; i += 2) {
        int2 e0 = __ldg(&g_edge[i]);
        int2 e1 = __ldg(&g_edge[i + 1]);
        float w0 = __int_as_float(e0.y), w1 = __int_as_float(e1.y);
        float4 a = __ldg(&g_xws1[(size_t)e0.x * 16 + c]);
        float4 b = __ldg(&g_xws1[(size_t)e1.x * 16 + c]);
        v.x += w0 * a.x + w1 * b.x;
        v.y += w0 * a.y + w1 * b.y;
        v.z += w0 * a.z + w1 * b.z;
        v.w += w0 * a.w + w1 * b.w;
    }
    if (i < end) {
        int2 e0 = __ldg(&g_edge[i]);
        float w0 = __int_as_float(e0.y);
        float4 a = __ldg(&g_xws1[(size_t)e0.x * 16 + c]);
        v.x += w0 * a.x; v.y += w0 * a.y; v.z += w0 * a.z; v.w += w0 * a.w;
    }
    float d = g_dis[node];
    float4 sv = g_xws1[(size_t)node * 16 + c];
    float4 bb = __ldg(&((const float4*)b1)[c]);
    float hx = fmaxf(fmaf(d, fmaf(d, sv.x, v.x), bb.x), 0.f);
    float hy = fmaxf(fmaf(d, fmaf(d, sv.y, v.y), bb.y), 0.f);
    float hz = fmaxf(fmaf(d, fmaf(d, sv.z, v.z), bb.z), 0.f);
    float hw = fmaxf(fmaf(d, fmaf(d, sv.w, v.w), bb.w), 0.f);
    float4 wf = g_wf4[c];
    float s = hx * wf.x + hy * wf.y + hz * wf.z + hw * wf.w;
#pragma unroll
    for (int o = 8; o > 0; o >>= 1) s += __shfl_down_sync(0xffffffffu, s, o);
    if (c == 0) g_p[node] = s;
}

// ---------------- head: out[b] = sigmoid(dis[j]*(sum ew'*p[src] + dis[j]*p[j]) + c) ----
__global__ void k_head(const int* __restrict__ join, float* __restrict__ out) {
    int warp = (blockIdx.x * blockDim.x + threadIdx.x) >> 5;
    int lane = threadIdx.x & 31;
    if (warp >= BJ) return;
    int j = join[warp];
    int beg = g_rowptr[j], end = g_rowptr[j + 1];
    float acc = 0.f;
    for (int i = beg + lane; i < end; i += 32) {
        int2 e = __ldg(&g_edge[i]);
        acc += __int_as_float(e.y) * __ldg(&g_p[e.x]);
    }
#pragma unroll
    for (int o = 16; o > 0; o >>= 1) acc += __shfl_down_sync(0xffffffffu, acc, o);
    if (lane == 0) {
        float d = g_dis[j];
        float z = d * fmaf(d, g_p[j], acc) + g_c;
        out[warp] = 1.0f / (1.0f + expf(-z));
    }
}

// ---------------- launch ----------------
extern "C" void kernel_launch(void* const* d_in, const int* in_sizes, int n_in,
                              void* d_out, int out_size) {
    (void)in_sizes; (void)n_in; (void)out_size;
    const float* x    = (const float*)d_in[0];
    const int*   eidx = (const int*)  d_in[1];
    const int*   join = (const int*)  d_in[2];
    const float* ew   = (const float*)d_in[3];
    const float* W1   = (const float*)d_in[4];
    const float* b1   = (const float*)d_in[5];
    const float* W2   = (const float*)d_in[6];
    const float* b2   = (const float*)d_in[7];
    const float* Wl   = (const float*)d_in[8];
    const float* bl   = (const float*)d_in[9];
    float*       out  = (float*)d_out;

    const int* src = eidx;
    const int* dst = eidx + EE;

    static cudaStream_t sA = 0;
    static cudaEvent_t evRoot = 0, evA = 0;
    static bool inited = false;
    if (!inited) {
        cudaStreamCreateWithFlags(&sA, cudaStreamNonBlocking);
        cudaEventCreateWithFlags(&evRoot, cudaEventDisableTiming);
        cudaEventCreateWithFlags(&evA, cudaEventDisableTiming);
        inited = true;
    }

    const int g1_smem = G1_SMEM_F4 * 16;              // 98816 B
    static bool attrSet = false;
    if (!attrSet) {
        cudaFuncSetAttribute(k_gemm1, cudaFuncAttributeMaxDynamicSharedMemorySize, g1_smem);
        attrSet = true;
    }

    const int nscan = (NN + SCAN_BLK - 1) / SCAN_BLK; // 98

    // fork: side stream A runs gemm1 + wf concurrently with the CSR chain (stream 0)
    cudaEventRecord(evRoot, 0);
    cudaStreamWaitEvent(sA, evRoot, 0);

    k_init       <<<(NN + 255) / 256, 256>>>();                        // #0 (B)
    k_hist       <<<EE / 256, 256>>>(dst, ew);                         // #1 (B)
    k_scan1      <<<nscan, SCAN_BLK>>>();                              // #2 (B)
    k_gemm1      <<<NN / 32, 128, g1_smem, sA>>>(x, W1);               // #3 (A) <- profiled
    k_wf         <<<1, 128, 0, sA>>>(W2, b2, Wl, bl);                  // #4 (A)
    k_scan2      <<<1, 128>>>(nscan);                                  // #5 (B)
    k_scan_apply <<<(NN + 255) / 256, 256>>>();                        // #6 (B)
    k_fill       <<<EE / 256, 256>>>(src, dst, ew);                    // #7 (B)

    cudaEventRecord(evA, sA);
    cudaStreamWaitEvent(0, evA, 0);                                    // join A -> B

    k_agg1q      <<<(NN * 16 + 255) / 256, 256>>>(b1);                 // #8
    k_head       <<<(BJ * 32) / 256, 256>>>(join, out);                // #9
}

// round 7
// speedup vs baseline: 2.6952x; 1.0011x over previous
#include <cuda_runtime.h>
#include <math.h>

#define NN   100000
#define EE   1600000
#define FIN  256
#define H1   64
#define H2   128
#define BJ   4096

// ---------------- scratch (device globals) ----------------
__device__ float  g_deg[NN];
__device__ float  g_dis[NN];
__device__ int    g_cnt[NN];
__device__ int    g_rowptr[NN + 1];
__device__ int    g_cursor[NN];
__device__ int    g_blksum[128];
__device__ int2   g_edge[EE];              // (src, ew*dis[src]) grouped by dst
__device__ float4 g_xws1[NN * (H1 / 4)];   // raw x @ W1   [N,64]
__device__ float  g_p[NN];                 // h1[n] . wf
__device__ float4 g_wf4[H1 / 4];           // wf = W2 @ Wl  [64]
__device__ float  g_c;                     // b2.Wl + bl

// ---------------- f32x2 helpers (sm_103a packed fp32) ----------------
__device__ __forceinline__ unsigned long long f32x2_fma(unsigned long long a,
                                                        unsigned long long b,
                                                        unsigned long long c) {
    unsigned long long d;
    asm("fma.rn.f32x2 %0, %1, %2, %3;" : "=l"(d) : "l"(a), "l"(b), "l"(c));
    return d;
}
__device__ __forceinline__ unsigned long long f32x2_bcast(float v) {
    unsigned long long d;
    asm("mov.b64 %0, {%1, %2};" : "=l"(d) : "f"(v), "f"(v));
    return d;
}
__device__ __forceinline__ float2 f32x2_unpack(unsigned long long v) {
    float lo, hi;
    asm("mov.b64 {%0, %1}, %2;" : "=f"(lo), "=f"(hi) : "l"(v));
    return make_float2(lo, hi);
}

// ---------------- init / degree ----------------
__global__ void k_init() {
    int i = blockIdx.x * blockDim.x + threadIdx.x;
    if (i < NN) { g_deg[i] = 1.0f; g_cnt[i] = 0; }
}

__global__ void k_hist(const int* __restrict__ dst, const float* __restrict__ ew) {
    int e = blockIdx.x * blockDim.x + threadIdx.x;
    if (e < EE) {
        int d = dst[e];
        atomicAdd(&g_cnt[d], 1);
        atomicAdd(&g_deg[d], ew[e]);
    }
}

// ---------------- 2-level exclusive scan of g_cnt -> g_rowptr ----------------
#define SCAN_BLK 1024
__global__ void k_scan1() {
    __shared__ int sm[SCAN_BLK];
    int t = threadIdx.x;
    int i = blockIdx.x * SCAN_BLK + t;
    int a = (i < NN) ? g_cnt[i] : 0;
    sm[t] = a;
    __syncthreads();
#pragma unroll
    for (int off = 1; off < SCAN_BLK; off <<= 1) {
        int v = (t >= off) ? sm[t - off] : 0;
        __syncthreads();
        sm[t] += v;
        __syncthreads();
    }
    if (i < NN) g_rowptr[i] = sm[t] - a;
    if (t == SCAN_BLK - 1) g_blksum[blockIdx.x] = sm[t];
}

__global__ void k_scan2(int nblk) {
    __shared__ int s[128];
    int t = threadIdx.x;
    if (t < nblk) s[t] = g_blksum[t];
    __syncthreads();
    if (t == 0) {
        int run = 0;
        for (int b = 0; b < nblk; b++) { int v = s[b]; s[b] = run; run += v; }
    }
    __syncthreads();
    if (t < nblk) g_blksum[t] = s[t];
}

// rowptr finalize + cursor init + dis (fused)
__global__ void k_scan_apply() {
    int i = blockIdx.x * blockDim.x + threadIdx.x;
    if (i < NN) {
        int r = g_rowptr[i] + g_blksum[i >> 10];
        g_rowptr[i] = r;
        g_cursor[i] = r;
        g_dis[i] = rsqrtf(g_deg[i]);
    }
    if (i == 0) g_rowptr[NN] = EE;
}

// fill edges grouped by dst, folding dis[src] into the weight
__global__ void k_fill(const int* __restrict__ src, const int* __restrict__ dst,
                       const float* __restrict__ ew) {
    int e = blockIdx.x * blockDim.x + threadIdx.x;
    if (e < EE) {
        int d = dst[e];
        int s = src[e];
        int p = atomicAdd(&g_cursor[d], 1);
        g_edge[p] = make_int2(s, __float_as_int(ew[e] * g_dis[s]));
    }
}

// ---------------- wf = W2 @ Wl, c = b2.Wl + bl ----------------
__global__ void k_wf(const float* __restrict__ W2, const float* __restrict__ b2,
                     const float* __restrict__ Wl, const float* __restrict__ bl) {
    __shared__ float sWl[H2];
    __shared__ float red[H2];
    int t = threadIdx.x;   // 128
    sWl[t] = Wl[t];
    __syncthreads();
    if (t < H1) {
        float s = 0.f;
#pragma unroll 8
        for (int m = 0; m < H2; m++) s += W2[t * H2 + m] * sWl[m];
        ((float*)g_wf4)[t] = s;
    }
    red[t] = b2[t] * sWl[t];
    __syncthreads();
    if (t == 0) {
        float s = 0.f;
        for (int m = 0; m < H2; m++) s += red[m];
        g_c = s + bl[0];
    }
}

// ---------------- GEMM1: xws1 = x @ W1 (raw) ----------------
// 128 thr, 128 rows x 64 cols per CTA, 8x8 thread tile.
// W full (64KB, permuted, conflict-free); x double-buffered k-chunks of 32.
#define CK 32                               // k-chunk
#define XROWSTRIDE 9                        // float4 units per smem x row (8 + 1 pad)
#define G1_SMEM_BYTES (FIN * H1 * 4 + 2 * 128 * XROWSTRIDE * 16)   // 65536 + 36864
__global__ void __launch_bounds__(128, 2) k_gemm1(const float* __restrict__ x,
                                                  const float* __restrict__ W1) {
    extern __shared__ float4 sm4[];
    float4* sW = sm4;                       // [256][16] permuted 16B units
    float4* sX = sm4 + FIN * 16;            // 2 x [128][XROWSTRIDE]
    const int t  = threadIdx.x;
    const int cg = t & 7;                   // 8 cols each
    const int rg = t >> 3;                  // 16 row-groups; rows rg + 16*i

    // ---- load W permuted: global f4 j in row k -> smem unit k*16 + (j&1)*8 + (j>>1)
    // unit m (m<8)   = cols 8m..8m+3
    // unit 8+m       = cols 8m+4..8m+7
    const float4* W4 = (const float4*)W1;
#pragma unroll
    for (int it = 0; it < 32; it++) {
        int idx = t + it * 128;             // 0..4095
        int k = idx >> 4, j = idx & 15;
        sW[k * 16 + ((j & 1) << 3) + (j >> 1)] = W4[idx];
    }

    const int rb = blockIdx.x * 128;
    const float4* X4 = (const float4*)x;    // 64 f4 per row

    // ---- load chunk 0
#pragma unroll
    for (int it = 0; it < 8; it++) {
        int idx = t + it * 128;             // 0..1023
        int row = idx >> 3, j = idx & 7;
        int grow = rb + row; if (grow >= NN) grow = NN - 1;
        sX[row * XROWSTRIDE + j] = __ldg(&X4[(size_t)grow * 64 + j]);
    }
    __syncthreads();

    unsigned long long acc[8][4];
#pragma unroll
    for (int i = 0; i < 8; i++)
#pragma unroll
        for (int c = 0; c < 4; c++) acc[i][c] = 0ull;

    const ulonglong2* sWp = (const ulonglong2*)sW;

#pragma unroll 1
    for (int ch = 0; ch < FIN / CK; ch++) {     // 8 chunks
        float4* sXb = sX + (ch & 1) * 128 * XROWSTRIDE;
        float4* sXn = sX + ((ch + 1) & 1) * 128 * XROWSTRIDE;

        // prefetch next chunk into registers
        float4 pf[8];
        if (ch < 7) {
#pragma unroll
            for (int it = 0; it < 8; it++) {
                int idx = t + it * 128;
                int row = idx >> 3, j = idx & 7;
                int grow = rb + row; if (grow >= NN) grow = NN - 1;
                pf[it] = __ldg(&X4[(size_t)grow * 64 + (ch + 1) * 8 + j]);
            }
        }

        const int kbase = ch * CK;
#pragma unroll 2
        for (int k4 = 0; k4 < CK / 4; k4++) {   // 8 k4 per chunk
            float4 xv[8];
#pragma unroll
            for (int i = 0; i < 8; i++)
                xv[i] = sXb[(rg + 16 * i) * XROWSTRIDE + k4];
#pragma unroll
            for (int kk = 0; kk < 4; kk++) {
                int k = kbase + k4 * 4 + kk;
                ulonglong2 wa = sWp[k * 16 + cg];          // cols 8cg..8cg+3
                ulonglong2 wb = sWp[k * 16 + 8 + cg];      // cols 8cg+4..8cg+7
#pragma unroll
                for (int i = 0; i < 8; i++) {
                    float xs = (kk == 0) ? xv[i].x : (kk == 1) ? xv[i].y
                             : (kk == 2) ? xv[i].z : xv[i].w;
                    unsigned long long xp = f32x2_bcast(xs);
                    acc[i][0] = f32x2_fma(xp, wa.x, acc[i][0]);
                    acc[i][1] = f32x2_fma(xp, wa.y, acc[i][1]);
                    acc[i][2] = f32x2_fma(xp, wb.x, acc[i][2]);
                    acc[i][3] = f32x2_fma(xp, wb.y, acc[i][3]);
                }
            }
        }

        if (ch < 7) {
#pragma unroll
            for (int it = 0; it < 8; it++) {
                int idx = t + it * 128;
                int row = idx >> 3, j = idx & 7;
                sXn[row * XROWSTRIDE + j] = pf[it];
            }
            __syncthreads();
        }
    }

    // ---- epilogue: 8 rows x 8 cols per thread
#pragma unroll
    for (int i = 0; i < 8; i++) {
        int row = rb + rg + 16 * i;
        if (row < NN) {
            float2 a0 = f32x2_unpack(acc[i][0]);
            float2 a1 = f32x2_unpack(acc[i][1]);
            float2 a2 = f32x2_unpack(acc[i][2]);
            float2 a3 = f32x2_unpack(acc[i][3]);
            g_xws1[(size_t)row * 16 + cg * 2 + 0] = make_float4(a0.x, a0.y, a1.x, a1.y);
            g_xws1[(size_t)row * 16 + cg * 2 + 1] = make_float4(a2.x, a2.y, a3.x, a3.y);
        }
    }
}

// -------- agg1q: v = sum ew'*xw[src]; h1 = relu(dis*(v + dis*xw[n]) + b1);
//          p[n] = h1 . wf.  16 lanes/node. --------
__global__ void k_agg1q(const float* __restrict__ b1) {
    int gt = blockIdx.x * blockDim.x + threadIdx.x;
    int node = gt >> 4;
    int c = gt & 15;
    if (node >= NN) return;
    int beg = g_rowptr[node], end = g_rowptr[node + 1];
    float4 v = make_float4(0.f, 0.f, 0.f, 0.f);
    int i = beg;
    for (; i + 1 < end; i += 2) {
        int2 e0 = __ldg(&g_edge[i]);
        int2 e1 = __ldg(&g_edge[i + 1]);
        float w0 = __int_as_float(e0.y), w1 = __int_as_float(e1.y);
        float4 a = __ldg(&g_xws1[(size_t)e0.x * 16 + c]);
        float4 b = __ldg(&g_xws1[(size_t)e1.x * 16 + c]);
        v.x += w0 * a.x + w1 * b.x;
        v.y += w0 * a.y + w1 * b.y;
        v.z += w0 * a.z + w1 * b.z;
        v.w += w0 * a.w + w1 * b.w;
    }
    if (i < end) {
        int2 e0 = __ldg(&g_edge[i]);
        float w0 = __int_as_float(e0.y);
        float4 a = __ldg(&g_xws1[(size_t)e0.x * 16 + c]);
        v.x += w0 * a.x; v.y += w0 * a.y; v.z += w0 * a.z; v.w += w0 * a.w;
    }
    float d = g_dis[node];
    float4 sv = g_xws1[(size_t)node * 16 + c];
    float4 bb = __ldg(&((const float4*)b1)[c]);
    float hx = fmaxf(fmaf(d, fmaf(d, sv.x, v.x), bb.x), 0.f);
    float hy = fmaxf(fmaf(d, fmaf(d, sv.y, v.y), bb.y), 0.f);
    float hz = fmaxf(fmaf(d, fmaf(d, sv.z, v.z), bb.z), 0.f);
    float hw = fmaxf(fmaf(d, fmaf(d, sv.w, v.w), bb.w), 0.f);
    float4 wf = g_wf4[c];
    float s = hx * wf.x + hy * wf.y + hz * wf.z + hw * wf.w;
#pragma unroll
    for (int o = 8; o > 0; o >>= 1) s += __shfl_down_sync(0xffffffffu, s, o);
    if (c == 0) g_p[node] = s;
}

// ---------------- head: out[b] = sigmoid(dis[j]*(sum ew'*p[src] + dis[j]*p[j]) + c) ----
__global__ void k_head(const int* __restrict__ join, float* __restrict__ out) {
    int warp = (blockIdx.x * blockDim.x + threadIdx.x) >> 5;
    int lane = threadIdx.x & 31;
    if (warp >= BJ) return;
    int j = join[warp];
    int beg = g_rowptr[j], end = g_rowptr[j + 1];
    float acc = 0.f;
    for (int i = beg + lane; i < end; i += 32) {
        int2 e = __ldg(&g_edge[i]);
        acc += __int_as_float(e.y) * __ldg(&g_p[e.x]);
    }
#pragma unroll
    for (int o = 16; o > 0; o >>= 1) acc += __shfl_down_sync(0xffffffffu, acc, o);
    if (lane == 0) {
        float d = g_dis[j];
        float z = d * fmaf(d, g_p[j], acc) + g_c;
        out[warp] = 1.0f / (1.0f + expf(-z));
    }
}

// ---------------- launch ----------------
extern "C" void kernel_launch(void* const* d_in, const int* in_sizes, int n_in,
                              void* d_out, int out_size) {
    (void)in_sizes; (void)n_in; (void)out_size;
    const float* x    = (const float*)d_in[0];
    const int*   eidx = (const int*)  d_in[1];
    const int*   join = (const int*)  d_in[2];
    const float* ew   = (const float*)d_in[3];
    const float* W1   = (const float*)d_in[4];
    const float* b1   = (const float*)d_in[5];
    const float* W2   = (const float*)d_in[6];
    const float* b2   = (const float*)d_in[7];
    const float* Wl   = (const float*)d_in[8];
    const float* bl   = (const float*)d_in[9];
    float*       out  = (float*)d_out;

    const int* src = eidx;
    const int* dst = eidx + EE;

    static cudaStream_t sA = 0;
    static cudaEvent_t evRoot = 0, evA = 0;
    static bool inited = false;
    if (!inited) {
        cudaStreamCreateWithFlags(&sA, cudaStreamNonBlocking);
        cudaEventCreateWithFlags(&evRoot, cudaEventDisableTiming);
        cudaEventCreateWithFlags(&evA, cudaEventDisableTiming);
        cudaFuncSetAttribute(k_gemm1, cudaFuncAttributeMaxDynamicSharedMemorySize,
                             G1_SMEM_BYTES);
        inited = true;
    }

    const int nscan = (NN + SCAN_BLK - 1) / SCAN_BLK; // 98
    const int g1_blocks = (NN + 127) / 128;           // 782

    // fork: side stream A runs gemm1 + wf concurrently with the CSR chain (stream 0)
    cudaEventRecord(evRoot, 0);
    cudaStreamWaitEvent(sA, evRoot, 0);

    k_init       <<<(NN + 255) / 256, 256>>>();                        // #0 (B)
    k_hist       <<<EE / 256, 256>>>(dst, ew);                         // #1 (B)
    k_scan1      <<<nscan, SCAN_BLK>>>();                              // #2 (B)
    k_gemm1      <<<g1_blocks, 128, G1_SMEM_BYTES, sA>>>(x, W1);       // #3 (A) <- profiled
    k_wf         <<<1, 128, 0, sA>>>(W2, b2, Wl, bl);                  // #4 (A)
    k_scan2      <<<1, 128>>>(nscan);                                  // #5 (B)
    k_scan_apply <<<(NN + 255) / 256, 256>>>();                        // #6 (B)
    k_fill       <<<EE / 256, 256>>>(src, dst, ew);                    // #7 (B)

    cudaEventRecord(evA, sA);
    cudaStreamWaitEvent(0, evA, 0);                                    // join A -> B

    k_agg1q      <<<(NN * 16 + 255) / 256, 256>>>(b1);                 // #8
    k_head       <<<(BJ * 32) / 256, 256>>>(join, out);                // #9
}

// round 8
// speedup vs baseline: 2.6971x; 1.0007x over previous
#include <cuda_runtime.h>
#include <cuda_fp16.h>
#include <math.h>

#define NN   100000
#define EE   1600000
#define FIN  256
#define H1   64
#define H2   128
#define BJ   4096

// ---------------- scratch (device globals) ----------------
__device__ float  g_deg[NN];
__device__ float  g_dis[NN];
__device__ int    g_cnt[NN];
__device__ int    g_rowptr[NN + 1];
__device__ int    g_cursor[NN];
__device__ int    g_blksum[128];
__device__ __align__(16) int2 g_edge[EE];   // (src, ew*dis[src]) grouped by dst
__device__ __half2 g_xh1[NN * (H1 / 2)];    // x @ W1 in fp16  [N,64]
__device__ float  g_p[NN];                  // h1[n] . wf
__device__ float  g_wf[H1];                 // wf = W2 @ Wl  [64]
__device__ float  g_c;                      // b2.Wl + bl

// ---------------- f32x2 helpers (sm_103a packed fp32) ----------------
__device__ __forceinline__ unsigned long long f32x2_fma(unsigned long long a,
                                                        unsigned long long b,
                                                        unsigned long long c) {
    unsigned long long d;
    asm("fma.rn.f32x2 %0, %1, %2, %3;" : "=l"(d) : "l"(a), "l"(b), "l"(c));
    return d;
}
__device__ __forceinline__ unsigned long long f32x2_bcast(float v) {
    unsigned long long d;
    asm("mov.b64 %0, {%1, %2};" : "=l"(d) : "f"(v), "f"(v));
    return d;
}
__device__ __forceinline__ float2 f32x2_unpack(unsigned long long v) {
    float lo, hi;
    asm("mov.b64 {%0, %1}, %2;" : "=f"(lo), "=f"(hi) : "l"(v));
    return make_float2(lo, hi);
}

// ---------------- init / degree ----------------
__global__ void k_init() {
    int i = blockIdx.x * blockDim.x + threadIdx.x;
    if (i < NN) { g_deg[i] = 1.0f; g_cnt[i] = 0; }
}

__global__ void k_hist(const int* __restrict__ dst, const float* __restrict__ ew) {
    int e = blockIdx.x * blockDim.x + threadIdx.x;
    if (e < EE) {
        int d = dst[e];
        atomicAdd(&g_cnt[d], 1);
        atomicAdd(&g_deg[d], ew[e]);
    }
}

// ---------------- 2-level exclusive scan of g_cnt -> g_rowptr ----------------
#define SCAN_BLK 1024
__global__ void k_scan1() {
    __shared__ int sm[SCAN_BLK];
    int t = threadIdx.x;
    int i = blockIdx.x * SCAN_BLK + t;
    int a = (i < NN) ? g_cnt[i] : 0;
    sm[t] = a;
    __syncthreads();
#pragma unroll
    for (int off = 1; off < SCAN_BLK; off <<= 1) {
        int v = (t >= off) ? sm[t - off] : 0;
        __syncthreads();
        sm[t] += v;
        __syncthreads();
    }
    if (i < NN) g_rowptr[i] = sm[t] - a;
    if (t == SCAN_BLK - 1) g_blksum[blockIdx.x] = sm[t];
}

__global__ void k_scan2(int nblk) {
    __shared__ int s[128];
    int t = threadIdx.x;
    if (t < nblk) s[t] = g_blksum[t];
    __syncthreads();
    if (t == 0) {
        int run = 0;
        for (int b = 0; b < nblk; b++) { int v = s[b]; s[b] = run; run += v; }
    }
    __syncthreads();
    if (t < nblk) g_blksum[t] = s[t];
}

// rowptr finalize + cursor init + dis (fused)
__global__ void k_scan_apply() {
    int i = blockIdx.x * blockDim.x + threadIdx.x;
    if (i < NN) {
        int r = g_rowptr[i] + g_blksum[i >> 10];
        g_rowptr[i] = r;
        g_cursor[i] = r;
        g_dis[i] = rsqrtf(g_deg[i]);
    }
    if (i == 0) g_rowptr[NN] = EE;
}

// fill edges grouped by dst, folding dis[src] into the weight
__global__ void k_fill(const int* __restrict__ src, const int* __restrict__ dst,
                       const float* __restrict__ ew) {
    int e = blockIdx.x * blockDim.x + threadIdx.x;
    if (e < EE) {
        int d = dst[e];
        int s = src[e];
        int p = atomicAdd(&g_cursor[d], 1);
        g_edge[p] = make_int2(s, __float_as_int(ew[e] * g_dis[s]));
    }
}

// ---------------- wf = W2 @ Wl, c = b2.Wl + bl ----------------
__global__ void k_wf(const float* __restrict__ W2, const float* __restrict__ b2,
                     const float* __restrict__ Wl, const float* __restrict__ bl) {
    __shared__ float sWl[H2];
    __shared__ float red[H2];
    int t = threadIdx.x;   // 128
    sWl[t] = Wl[t];
    __syncthreads();
    if (t < H1) {
        float s = 0.f;
#pragma unroll 8
        for (int m = 0; m < H2; m++) s += W2[t * H2 + m] * sWl[m];
        g_wf[t] = s;
    }
    red[t] = b2[t] * sWl[t];
    __syncthreads();
    if (t == 0) {
        float s = 0.f;
        for (int m = 0; m < H2; m++) s += red[m];
        g_c = s + bl[0];
    }
}

// ---------------- GEMM1: xh1 = fp16(x @ W1) ----------------
// 128 thr, 128 rows x 64 cols per CTA, 8x8 thread tile.
// W full (64KB, permuted, conflict-free); x double-buffered k-chunks of 32.
#define CK 32                               // k-chunk
#define XROWSTRIDE 9                        // float4 units per smem x row (8 + 1 pad)
#define G1_SMEM_BYTES (FIN * H1 * 4 + 2 * 128 * XROWSTRIDE * 16)   // 65536 + 36864
__global__ void __launch_bounds__(128, 2) k_gemm1(const float* __restrict__ x,
                                                  const float* __restrict__ W1) {
    extern __shared__ float4 sm4[];
    float4* sW = sm4;                       // [256][16] permuted 16B units
    float4* sX = sm4 + FIN * 16;            // 2 x [128][XROWSTRIDE]
    const int t  = threadIdx.x;
    const int cg = t & 7;                   // 8 cols each
    const int rg = t >> 3;                  // 16 row-groups; rows rg + 16*i

    // ---- load W permuted: global f4 j in row k -> smem unit k*16 + (j&1)*8 + (j>>1)
    const float4* W4 = (const float4*)W1;
#pragma unroll
    for (int it = 0; it < 32; it++) {
        int idx = t + it * 128;             // 0..4095
        int k = idx >> 4, j = idx & 15;
        sW[k * 16 + ((j & 1) << 3) + (j >> 1)] = W4[idx];
    }

    const int rb = blockIdx.x * 128;
    const float4* X4 = (const float4*)x;    // 64 f4 per row

    // ---- load chunk 0
#pragma unroll
    for (int it = 0; it < 8; it++) {
        int idx = t + it * 128;             // 0..1023
        int row = idx >> 3, j = idx & 7;
        int grow = rb + row; if (grow >= NN) grow = NN - 1;
        sX[row * XROWSTRIDE + j] = __ldg(&X4[(size_t)grow * 64 + j]);
    }
    __syncthreads();

    unsigned long long acc[8][4];
#pragma unroll
    for (int i = 0; i < 8; i++)
#pragma unroll
        for (int c = 0; c < 4; c++) acc[i][c] = 0ull;

    const ulonglong2* sWp = (const ulonglong2*)sW;

#pragma unroll 1
    for (int ch = 0; ch < FIN / CK; ch++) {     // 8 chunks
        float4* sXb = sX + (ch & 1) * 128 * XROWSTRIDE;
        float4* sXn = sX + ((ch + 1) & 1) * 128 * XROWSTRIDE;

        float4 pf[8];
        if (ch < 7) {
#pragma unroll
            for (int it = 0; it < 8; it++) {
                int idx = t + it * 128;
                int row = idx >> 3, j = idx & 7;
                int grow = rb + row; if (grow >= NN) grow = NN - 1;
                pf[it] = __ldg(&X4[(size_t)grow * 64 + (ch + 1) * 8 + j]);
            }
        }

        const int kbase = ch * CK;
#pragma unroll 2
        for (int k4 = 0; k4 < CK / 4; k4++) {   // 8 k4 per chunk
            float4 xv[8];
#pragma unroll
            for (int i = 0; i < 8; i++)
                xv[i] = sXb[(rg + 16 * i) * XROWSTRIDE + k4];
#pragma unroll
            for (int kk = 0; kk < 4; kk++) {
                int k = kbase + k4 * 4 + kk;
                ulonglong2 wa = sWp[k * 16 + cg];          // cols 8cg..8cg+3
                ulonglong2 wb = sWp[k * 16 + 8 + cg];      // cols 8cg+4..8cg+7
#pragma unroll
                for (int i = 0; i < 8; i++) {
                    float xs = (kk == 0) ? xv[i].x : (kk == 1) ? xv[i].y
                             : (kk == 2) ? xv[i].z : xv[i].w;
                    unsigned long long xp = f32x2_bcast(xs);
                    acc[i][0] = f32x2_fma(xp, wa.x, acc[i][0]);
                    acc[i][1] = f32x2_fma(xp, wa.y, acc[i][1]);
                    acc[i][2] = f32x2_fma(xp, wb.x, acc[i][2]);
                    acc[i][3] = f32x2_fma(xp, wb.y, acc[i][3]);
                }
            }
        }

        if (ch < 7) {
#pragma unroll
            for (int it = 0; it < 8; it++) {
                int idx = t + it * 128;
                int row = idx >> 3, j = idx & 7;
                sXn[row * XROWSTRIDE + j] = pf[it];
            }
            __syncthreads();
        }
    }

    // ---- epilogue: 8 rows x 8 cols per thread -> packed fp16 (one STG.128)
    uint4* XH4 = (uint4*)g_xh1;             // node*8 + cg : 4 half2 = 8 cols
#pragma unroll
    for (int i = 0; i < 8; i++) {
        int row = rb + rg + 16 * i;
        if (row < NN) {
            float2 a0 = f32x2_unpack(acc[i][0]);
            float2 a1 = f32x2_unpack(acc[i][1]);
            float2 a2 = f32x2_unpack(acc[i][2]);
            float2 a3 = f32x2_unpack(acc[i][3]);
            __half2 h0 = __floats2half2_rn(a0.x, a0.y);
            __half2 h1 = __floats2half2_rn(a1.x, a1.y);
            __half2 h2 = __floats2half2_rn(a2.x, a2.y);
            __half2 h3 = __floats2half2_rn(a3.x, a3.y);
            uint4 pack;
            pack.x = *(unsigned int*)&h0;
            pack.y = *(unsigned int*)&h1;
            pack.z = *(unsigned int*)&h2;
            pack.w = *(unsigned int*)&h3;
            XH4[(size_t)row * 8 + cg] = pack;
        }
    }
}

// -------- agg1q: warp per node. v = sum ew'*xw[src] (fp16 rows);
//          h1 = relu(dis*(v + dis*xw[n]) + b1); p[n] = h1 . wf. --------
__global__ void k_agg1q(const float* __restrict__ b1) {
    int warp = (blockIdx.x * blockDim.x + threadIdx.x) >> 5;
    int lane = threadIdx.x & 31;
    if (warp >= NN) return;
    const int node = warp;
    int beg = g_rowptr[node], end = g_rowptr[node + 1];
    float2 v = make_float2(0.f, 0.f);
    const __half2* XH = g_xh1;

    int i = beg;
    if ((i & 1) && i < end) {               // align to 16B for int4 loads
        int2 e = __ldg(&g_edge[i]);
        float w = __int_as_float(e.y);
        float2 a = __half22float2(__ldg(&XH[(size_t)e.x * 32 + lane]));
        v.x += w * a.x; v.y += w * a.y;
        i++;
    }
    for (; i + 1 < end; i += 2) {
        int4 ee = __ldg((const int4*)&g_edge[i]);   // 2 edges
        float w0 = __int_as_float(ee.y), w1 = __int_as_float(ee.w);
        float2 a = __half22float2(__ldg(&XH[(size_t)ee.x * 32 + lane]));
        float2 b = __half22float2(__ldg(&XH[(size_t)ee.z * 32 + lane]));
        v.x += w0 * a.x + w1 * b.x;
        v.y += w0 * a.y + w1 * b.y;
    }
    if (i < end) {
        int2 e = __ldg(&g_edge[i]);
        float w = __int_as_float(e.y);
        float2 a = __half22float2(__ldg(&XH[(size_t)e.x * 32 + lane]));
        v.x += w * a.x; v.y += w * a.y;
    }

    float d = g_dis[node];
    float2 sv = __half22float2(XH[(size_t)node * 32 + lane]);
    float2 bb = __ldg(&((const float2*)b1)[lane]);
    float hx = fmaxf(fmaf(d, fmaf(d, sv.x, v.x), bb.x), 0.f);
    float hy = fmaxf(fmaf(d, fmaf(d, sv.y, v.y), bb.y), 0.f);
    float2 wf = ((const float2*)g_wf)[lane];
    float s = hx * wf.x + hy * wf.y;
#pragma unroll
    for (int o = 16; o > 0; o >>= 1) s += __shfl_down_sync(0xffffffffu, s, o);
    if (lane == 0) g_p[node] = s;
}

// ---------------- head: out[b] = sigmoid(dis[j]*(sum ew'*p[src] + dis[j]*p[j]) + c) ----
__global__ void k_head(const int* __restrict__ join, float* __restrict__ out) {
    int warp = (blockIdx.x * blockDim.x + threadIdx.x) >> 5;
    int lane = threadIdx.x & 31;
    if (warp >= BJ) return;
    int j = join[warp];
    int beg = g_rowptr[j], end = g_rowptr[j + 1];
    float acc = 0.f;
    for (int i = beg + lane; i < end; i += 32) {
        int2 e = __ldg(&g_edge[i]);
        acc += __int_as_float(e.y) * __ldg(&g_p[e.x]);
    }
#pragma unroll
    for (int o = 16; o > 0; o >>= 1) acc += __shfl_down_sync(0xffffffffu, acc, o);
    if (lane == 0) {
        float d = g_dis[j];
        float z = d * fmaf(d, g_p[j], acc) + g_c;
        out[warp] = 1.0f / (1.0f + expf(-z));
    }
}

// ---------------- launch ----------------
extern "C" void kernel_launch(void* const* d_in, const int* in_sizes, int n_in,
                              void* d_out, int out_size) {
    (void)in_sizes; (void)n_in; (void)out_size;
    const float* x    = (const float*)d_in[0];
    const int*   eidx = (const int*)  d_in[1];
    const int*   join = (const int*)  d_in[2];
    const float* ew   = (const float*)d_in[3];
    const float* W1   = (const float*)d_in[4];
    const float* b1   = (const float*)d_in[5];
    const float* W2   = (const float*)d_in[6];
    const float* b2   = (const float*)d_in[7];
    const float* Wl   = (const float*)d_in[8];
    const float* bl   = (const float*)d_in[9];
    float*       out  = (float*)d_out;

    const int* src = eidx;
    const int* dst = eidx + EE;

    static cudaStream_t sA = 0;
    static cudaEvent_t evRoot = 0, evA = 0;
    static bool inited = false;
    if (!inited) {
        cudaStreamCreateWithFlags(&sA, cudaStreamNonBlocking);
        cudaEventCreateWithFlags(&evRoot, cudaEventDisableTiming);
        cudaEventCreateWithFlags(&evA, cudaEventDisableTiming);
        cudaFuncSetAttribute(k_gemm1, cudaFuncAttributeMaxDynamicSharedMemorySize,
                             G1_SMEM_BYTES);
        inited = true;
    }

    const int nscan = (NN + SCAN_BLK - 1) / SCAN_BLK; // 98
    const int g1_blocks = (NN + 127) / 128;           // 782

    // fork: side stream A runs gemm1 + wf concurrently with the CSR chain (stream 0)
    cudaEventRecord(evRoot, 0);
    cudaStreamWaitEvent(sA, evRoot, 0);

    k_init       <<<(NN + 255) / 256, 256>>>();                        // #0 (B)
    k_hist       <<<EE / 256, 256>>>(dst, ew);                         // #1 (B)
    k_scan1      <<<nscan, SCAN_BLK>>>();                              // #2 (B)
    k_gemm1      <<<g1_blocks, 128, G1_SMEM_BYTES, sA>>>(x, W1);       // #3 (A) <- profiled
    k_wf         <<<1, 128, 0, sA>>>(W2, b2, Wl, bl);                  // #4 (A)
    k_scan2      <<<1, 128>>>(nscan);                                  // #5 (B)
    k_scan_apply <<<(NN + 255) / 256, 256>>>();                        // #6 (B)
    k_fill       <<<EE / 256, 256>>>(src, dst, ew);                    // #7 (B)

    cudaEventRecord(evA, sA);
    cudaStreamWaitEvent(0, evA, 0);                                    // join A -> B

    k_agg1q      <<<(NN * 32 + 255) / 256, 256>>>(b1);                 // #8
    k_head       <<<(BJ * 32) / 256, 256>>>(join, out);                // #9
}

// round 9
// speedup vs baseline: 2.8280x; 1.0485x over previous
#include <cuda_runtime.h>
#include <cuda_fp16.h>
#include <math.h>

#define NN   100000
#define EE   1600000
#define FIN  256
#define H1   64
#define H2   128
#define BJ   4096
#define NSCANB ((NN + 1023) / 1024)   // 98

// ---------------- scratch (device globals) ----------------
__device__ unsigned long long g_pk[NN];     // (count<<32) | fixpoint(sum ew * 2^23)
__device__ unsigned long long g_part[NSCANB]; // lookback state: (status<<32)|value
__device__ float  g_dis[NN];
__device__ int    g_rowptr[NN + 1];
__device__ int    g_pos[EE];                // edge position within its dst bucket
__device__ __align__(16) int2 g_edge[EE];   // (src, ew*dis[src]) grouped by dst
__device__ __half2 g_xh1[NN * (H1 / 2)];    // x @ W1 in fp16  [N,64]
__device__ float  g_p[NN];                  // h1[n] . wf
__device__ float  g_wf[H1];                 // wf = W2 @ Wl  [64]
__device__ float  g_c;                      // b2.Wl + bl

// ---------------- f32x2 helpers (sm_103a packed fp32) ----------------
__device__ __forceinline__ unsigned long long f32x2_fma(unsigned long long a,
                                                        unsigned long long b,
                                                        unsigned long long c) {
    unsigned long long d;
    asm("fma.rn.f32x2 %0, %1, %2, %3;" : "=l"(d) : "l"(a), "l"(b), "l"(c));
    return d;
}
__device__ __forceinline__ unsigned long long f32x2_bcast(float v) {
    unsigned long long d;
    asm("mov.b64 %0, {%1, %2};" : "=l"(d) : "f"(v), "f"(v));
    return d;
}
__device__ __forceinline__ float2 f32x2_unpack(unsigned long long v) {
    float lo, hi;
    asm("mov.b64 {%0, %1}, %2;" : "=f"(lo), "=f"(hi) : "l"(v));
    return make_float2(lo, hi);
}

// ---------------- init ----------------
__global__ void k_init() {
    int i = blockIdx.x * blockDim.x + threadIdx.x;
    if (i < NN) g_pk[i] = 0ull;
    if (i < NSCANB) g_part[i] = 0ull;
}

// ---------------- hist: one packed atomic per edge; position for free ----------------
__global__ void k_hist(const int* __restrict__ dst, const float* __restrict__ ew) {
    int e = blockIdx.x * blockDim.x + threadIdx.x;
    if (e < EE) {
        int d = dst[e];
        unsigned int fx = __float2uint_rn(ew[e] * 8388608.0f);   // 2^23 scale
        unsigned long long old =
            atomicAdd(&g_pk[d], (1ull << 32) | (unsigned long long)fx);
        g_pos[e] = (int)(old >> 32);
    }
}

// ---------------- single-pass scan (decoupled lookback) + dis ----------------
__global__ void __launch_bounds__(256) k_scan() {
    __shared__ unsigned int wsum[8];
    __shared__ unsigned int s_bpref;
    const int b = blockIdx.x, t = threadIdx.x;
    const int lane = t & 31, wid = t >> 5;
    const int base = b * 1024 + t * 4;

    unsigned int c[4]; float dl[4];
#pragma unroll
    for (int j = 0; j < 4; j++) {
        int i = base + j;
        unsigned long long pk = (i < NN) ? g_pk[i] : 0ull;
        c[j]  = (unsigned int)(pk >> 32);
        dl[j] = (float)(unsigned int)pk;
    }
    unsigned int t_tot = c[0] + c[1] + c[2] + c[3];
    unsigned int v = t_tot;
#pragma unroll
    for (int o = 1; o < 32; o <<= 1) {
        unsigned int u = __shfl_up_sync(0xffffffffu, v, o);
        if (lane >= o) v += u;
    }
    if (lane == 31) wsum[wid] = v;
    __syncthreads();
    if (t < 8) {
        unsigned int w = wsum[t];
#pragma unroll
        for (int o = 1; o < 8; o <<= 1) {
            unsigned int u = __shfl_up_sync(0xffu, w, o);
            if (t >= o) w += u;
        }
        wsum[t] = w;
    }
    __syncthreads();
    unsigned int wpref  = (wid > 0) ? wsum[wid - 1] : 0u;
    unsigned int t_excl = wpref + v - t_tot;
    unsigned int btot   = wsum[7];

    if (t == 0) {
        if (b > 0) {
            atomicExch(&g_part[b], (1ull << 32) | (unsigned long long)btot);
            unsigned int excl = 0;
            int pb = b - 1;
            while (true) {
                unsigned long long st = atomicAdd(&g_part[pb], 0ull);
                unsigned int status = (unsigned int)(st >> 32);
                if (status == 2u) { excl += (unsigned int)st; break; }
                if (status == 1u) { excl += (unsigned int)st; pb--; }
            }
            s_bpref = excl;
            atomicExch(&g_part[b], (2ull << 32) | (unsigned long long)(excl + btot));
        } else {
            s_bpref = 0u;
            atomicExch(&g_part[0], (2ull << 32) | (unsigned long long)btot);
        }
    }
    __syncthreads();
    unsigned int run = s_bpref + t_excl;
#pragma unroll
    for (int j = 0; j < 4; j++) {
        int i = base + j;
        if (i < NN) {
            g_rowptr[i] = (int)run;
            g_dis[i] = rsqrtf(1.0f + dl[j] * (1.0f / 8388608.0f));
        }
        run += c[j];
    }
    if (b == NSCANB - 1 && t == 255) g_rowptr[NN] = EE;
}

// ---------------- fill: no atomics; position precomputed by hist ----------------
__global__ void k_fill(const int* __restrict__ src, const int* __restrict__ dst,
                       const float* __restrict__ ew) {
    int e = blockIdx.x * blockDim.x + threadIdx.x;
    if (e < EE) {
        int d = dst[e];
        int s = src[e];
        int p = g_rowptr[d] + g_pos[e];
        g_edge[p] = make_int2(s, __float_as_int(ew[e] * g_dis[s]));
    }
}

// ---------------- wf = W2 @ Wl, c = b2.Wl + bl ----------------
__global__ void k_wf(const float* __restrict__ W2, const float* __restrict__ b2,
                     const float* __restrict__ Wl, const float* __restrict__ bl) {
    __shared__ float sWl[H2];
    __shared__ float red[H2];
    int t = threadIdx.x;   // 128
    sWl[t] = Wl[t];
    __syncthreads();
    if (t < H1) {
        float s = 0.f;
#pragma unroll 8
        for (int m = 0; m < H2; m++) s += W2[t * H2 + m] * sWl[m];
        g_wf[t] = s;
    }
    red[t] = b2[t] * sWl[t];
    __syncthreads();
    if (t == 0) {
        float s = 0.f;
        for (int m = 0; m < H2; m++) s += red[m];
        g_c = s + bl[0];
    }
}

// ---------------- GEMM1: xh1 = fp16(x @ W1) ----------------
#define CK 32
#define XROWSTRIDE 9
#define G1_SMEM_BYTES (FIN * H1 * 4 + 2 * 128 * XROWSTRIDE * 16)   // 102400
__global__ void __launch_bounds__(128, 2) k_gemm1(const float* __restrict__ x,
                                                  const float* __restrict__ W1) {
    extern __shared__ float4 sm4[];
    float4* sW = sm4;                       // [256][16] permuted 16B units
    float4* sX = sm4 + FIN * 16;            // 2 x [128][XROWSTRIDE]
    const int t  = threadIdx.x;
    const int cg = t & 7;
    const int rg = t >> 3;

    const float4* W4 = (const float4*)W1;
#pragma unroll
    for (int it = 0; it < 32; it++) {
        int idx = t + it * 128;
        int k = idx >> 4, j = idx & 15;
        sW[k * 16 + ((j & 1) << 3) + (j >> 1)] = W4[idx];
    }

    const int rb = blockIdx.x * 128;
    const float4* X4 = (const float4*)x;

#pragma unroll
    for (int it = 0; it < 8; it++) {
        int idx = t + it * 128;
        int row = idx >> 3, j = idx & 7;
        int grow = rb + row; if (grow >= NN) grow = NN - 1;
        sX[row * XROWSTRIDE + j] = __ldg(&X4[(size_t)grow * 64 + j]);
    }
    __syncthreads();

    unsigned long long acc[8][4];
#pragma unroll
    for (int i = 0; i < 8; i++)
#pragma unroll
        for (int c = 0; c < 4; c++) acc[i][c] = 0ull;

    const ulonglong2* sWp = (const ulonglong2*)sW;

#pragma unroll 1
    for (int ch = 0; ch < FIN / CK; ch++) {
        float4* sXb = sX + (ch & 1) * 128 * XROWSTRIDE;
        float4* sXn = sX + ((ch + 1) & 1) * 128 * XROWSTRIDE;

        float4 pf[8];
        if (ch < 7) {
#pragma unroll
            for (int it = 0; it < 8; it++) {
                int idx = t + it * 128;
                int row = idx >> 3, j = idx & 7;
                int grow = rb + row; if (grow >= NN) grow = NN - 1;
                pf[it] = __ldg(&X4[(size_t)grow * 64 + (ch + 1) * 8 + j]);
            }
        }

        const int kbase = ch * CK;
#pragma unroll 2
        for (int k4 = 0; k4 < CK / 4; k4++) {
            float4 xv[8];
#pragma unroll
            for (int i = 0; i < 8; i++)
                xv[i] = sXb[(rg + 16 * i) * XROWSTRIDE + k4];
#pragma unroll
            for (int kk = 0; kk < 4; kk++) {
                int k = kbase + k4 * 4 + kk;
                ulonglong2 wa = sWp[k * 16 + cg];
                ulonglong2 wb = sWp[k * 16 + 8 + cg];
#pragma unroll
                for (int i = 0; i < 8; i++) {
                    float xs = (kk == 0) ? xv[i].x : (kk == 1) ? xv[i].y
                             : (kk == 2) ? xv[i].z : xv[i].w;
                    unsigned long long xp = f32x2_bcast(xs);
                    acc[i][0] = f32x2_fma(xp, wa.x, acc[i][0]);
                    acc[i][1] = f32x2_fma(xp, wa.y, acc[i][1]);
                    acc[i][2] = f32x2_fma(xp, wb.x, acc[i][2]);
                    acc[i][3] = f32x2_fma(xp, wb.y, acc[i][3]);
                }
            }
        }

        if (ch < 7) {
#pragma unroll
            for (int it = 0; it < 8; it++) {
                int idx = t + it * 128;
                int row = idx >> 3, j = idx & 7;
                sXn[row * XROWSTRIDE + j] = pf[it];
            }
            __syncthreads();
        }
    }

    uint4* XH4 = (uint4*)g_xh1;
#pragma unroll
    for (int i = 0; i < 8; i++) {
        int row = rb + rg + 16 * i;
        if (row < NN) {
            float2 a0 = f32x2_unpack(acc[i][0]);
            float2 a1 = f32x2_unpack(acc[i][1]);
            float2 a2 = f32x2_unpack(acc[i][2]);
            float2 a3 = f32x2_unpack(acc[i][3]);
            __half2 h0 = __floats2half2_rn(a0.x, a0.y);
            __half2 h1 = __floats2half2_rn(a1.x, a1.y);
            __half2 h2 = __floats2half2_rn(a2.x, a2.y);
            __half2 h3 = __floats2half2_rn(a3.x, a3.y);
            uint4 pack;
            pack.x = *(unsigned int*)&h0;
            pack.y = *(unsigned int*)&h1;
            pack.z = *(unsigned int*)&h2;
            pack.w = *(unsigned int*)&h3;
            XH4[(size_t)row * 8 + cg] = pack;
        }
    }
}

// -------- agg1q: warp per node; fp16 rows --------
__global__ void k_agg1q(const float* __restrict__ b1) {
    int warp = (blockIdx.x * blockDim.x + threadIdx.x) >> 5;
    int lane = threadIdx.x & 31;
    if (warp >= NN) return;
    const int node = warp;
    int beg = g_rowptr[node], end = g_rowptr[node + 1];
    float2 v = make_float2(0.f, 0.f);
    const __half2* XH = g_xh1;

    int i = beg;
    if ((i & 1) && i < end) {
        int2 e = __ldg(&g_edge[i]);
        float w = __int_as_float(e.y);
        float2 a = __half22float2(__ldg(&XH[(size_t)e.x * 32 + lane]));
        v.x += w * a.x; v.y += w * a.y;
        i++;
    }
    for (; i + 1 < end; i += 2) {
        int4 ee = __ldg((const int4*)&g_edge[i]);
        float w0 = __int_as_float(ee.y), w1 = __int_as_float(ee.w);
        float2 a = __half22float2(__ldg(&XH[(size_t)ee.x * 32 + lane]));
        float2 b = __half22float2(__ldg(&XH[(size_t)ee.z * 32 + lane]));
        v.x += w0 * a.x + w1 * b.x;
        v.y += w0 * a.y + w1 * b.y;
    }
    if (i < end) {
        int2 e = __ldg(&g_edge[i]);
        float w = __int_as_float(e.y);
        float2 a = __half22float2(__ldg(&XH[(size_t)e.x * 32 + lane]));
        v.x += w * a.x; v.y += w * a.y;
    }

    float d = g_dis[node];
    float2 sv = __half22float2(XH[(size_t)node * 32 + lane]);
    float2 bb = __ldg(&((const float2*)b1)[lane]);
    float hx = fmaxf(fmaf(d, fmaf(d, sv.x, v.x), bb.x), 0.f);
    float hy = fmaxf(fmaf(d, fmaf(d, sv.y, v.y), bb.y), 0.f);
    float2 wf = ((const float2*)g_wf)[lane];
    float s = hx * wf.x + hy * wf.y;
#pragma unroll
    for (int o = 16; o > 0; o >>= 1) s += __shfl_down_sync(0xffffffffu, s, o);
    if (lane == 0) g_p[node] = s;
}

// ---------------- head ----------------
__global__ void k_head(const int* __restrict__ join, float* __restrict__ out) {
    int warp = (blockIdx.x * blockDim.x + threadIdx.x) >> 5;
    int lane = threadIdx.x & 31;
    if (warp >= BJ) return;
    int j = join[warp];
    int beg = g_rowptr[j], end = g_rowptr[j + 1];
    float acc = 0.f;
    for (int i = beg + lane; i < end; i += 32) {
        int2 e = __ldg(&g_edge[i]);
        acc += __int_as_float(e.y) * __ldg(&g_p[e.x]);
    }
#pragma unroll
    for (int o = 16; o > 0; o >>= 1) acc += __shfl_down_sync(0xffffffffu, acc, o);
    if (lane == 0) {
        float d = g_dis[j];
        float z = d * fmaf(d, g_p[j], acc) + g_c;
        out[warp] = 1.0f / (1.0f + expf(-z));
    }
}

// ---------------- launch ----------------
extern "C" void kernel_launch(void* const* d_in, const int* in_sizes, int n_in,
                              void* d_out, int out_size) {
    (void)in_sizes; (void)n_in; (void)out_size;
    const float* x    = (const float*)d_in[0];
    const int*   eidx = (const int*)  d_in[1];
    const int*   join = (const int*)  d_in[2];
    const float* ew   = (const float*)d_in[3];
    const float* W1   = (const float*)d_in[4];
    const float* b1   = (const float*)d_in[5];
    const float* W2   = (const float*)d_in[6];
    const float* b2   = (const float*)d_in[7];
    const float* Wl   = (const float*)d_in[8];
    const float* bl   = (const float*)d_in[9];
    float*       out  = (float*)d_out;

    const int* src = eidx;
    const int* dst = eidx + EE;

    static cudaStream_t sA = 0;
    static cudaEvent_t evRoot = 0, evA = 0;
    static bool inited = false;
    if (!inited) {
        cudaStreamCreateWithFlags(&sA, cudaStreamNonBlocking);
        cudaEventCreateWithFlags(&evRoot, cudaEventDisableTiming);
        cudaEventCreateWithFlags(&evA, cudaEventDisableTiming);
        cudaFuncSetAttribute(k_gemm1, cudaFuncAttributeMaxDynamicSharedMemorySize,
                             G1_SMEM_BYTES);
        inited = true;
    }

    const int g1_blocks = (NN + 127) / 128;           // 782

    // fork: side stream A runs gemm1 + wf concurrently with the CSR chain (stream 0)
    cudaEventRecord(evRoot, 0);
    cudaStreamWaitEvent(sA, evRoot, 0);

    k_init  <<<(NN + 255) / 256, 256>>>();                         // #0 (B)
    k_hist  <<<EE / 256, 256>>>(dst, ew);                          // #1 (B)
    k_scan  <<<NSCANB, 256>>>();                                   // #2 (B)
    k_fill  <<<EE / 256, 256>>>(src, dst, ew);                     // #3 (B) <- profiled
    k_gemm1 <<<g1_blocks, 128, G1_SMEM_BYTES, sA>>>(x, W1);        // #4 (A)
    k_wf    <<<1, 128, 0, sA>>>(W2, b2, Wl, bl);                   // #5 (A)

    cudaEventRecord(evA, sA);
    cudaStreamWaitEvent(0, evA, 0);                                // join A -> B

    k_agg1q <<<(NN * 32 + 255) / 256, 256>>>(b1);                  // #6
    k_head  <<<(BJ * 32) / 256, 256>>>(join, out);                 // #7
}

// round 11
// speedup vs baseline: 3.9271x; 1.3886x over previous
#include <cuda_runtime.h>
#include <cuda_fp16.h>
#include <math.h>

#define NN   100000
#define EE   1600000
#define FIN  256
#define H1   64
#define H2   128
#define BJ   4096
#define NSCANB ((NN + 1023) / 1024)   // 98

// ---------------- scratch (device globals) ----------------
__device__ unsigned long long g_pk[NN];       // (count<<32) | fix(sum ew * 2^23)
__device__ unsigned long long g_part[NSCANB]; // lookback: (status<<32)|value
__device__ float  g_dis[NN];
__device__ int    g_rowptr[NN + 1];
__device__ int    g_pos[EE];
__device__ __align__(16) int2 g_edge[EE];     // (src, ew*dis[src]) grouped by dst
__device__ __half2 g_xh1[NN * (H1 / 2)];      // x @ W1 in fp16  [N,64]
__device__ float  g_p[NN];                    // h1[n] . wf
__device__ float  g_wf[H1];                   // wf = W2 @ Wl
__device__ float  g_c;                        // b2.Wl + bl

// ---------------- init ----------------
__global__ void k_init() {
    int i = blockIdx.x * blockDim.x + threadIdx.x;
    if (i < NN) g_pk[i] = 0ull;
    if (i < NSCANB) g_part[i] = 0ull;
}

// ---------------- hist: one packed atomic per edge; position for free ----------------
__global__ void k_hist(const int* __restrict__ dst, const float* __restrict__ ew) {
    int e = blockIdx.x * blockDim.x + threadIdx.x;
    if (e < EE) {
        int d = dst[e];
        unsigned int fx = __float2uint_rn(ew[e] * 8388608.0f);
        unsigned long long old =
            atomicAdd(&g_pk[d], (1ull << 32) | (unsigned long long)fx);
        g_pos[e] = (int)(old >> 32);
    }
}

// ---------------- single-pass scan (decoupled lookback) + dis ----------------
__global__ void __launch_bounds__(256) k_scan() {
    __shared__ unsigned int wsum[8];
    __shared__ unsigned int s_bpref;
    const int b = blockIdx.x, t = threadIdx.x;
    const int lane = t & 31, wid = t >> 5;
    const int base = b * 1024 + t * 4;

    unsigned int c[4]; float dl[4];
#pragma unroll
    for (int j = 0; j < 4; j++) {
        int i = base + j;
        unsigned long long pk = (i < NN) ? g_pk[i] : 0ull;
        c[j]  = (unsigned int)(pk >> 32);
        dl[j] = (float)(unsigned int)pk;
    }
    unsigned int t_tot = c[0] + c[1] + c[2] + c[3];
    unsigned int v = t_tot;
#pragma unroll
    for (int o = 1; o < 32; o <<= 1) {
        unsigned int u = __shfl_up_sync(0xffffffffu, v, o);
        if (lane >= o) v += u;
    }
    if (lane == 31) wsum[wid] = v;
    __syncthreads();
    if (t < 8) {
        unsigned int w = wsum[t];
#pragma unroll
        for (int o = 1; o < 8; o <<= 1) {
            unsigned int u = __shfl_up_sync(0xffu, w, o);
            if (t >= o) w += u;
        }
        wsum[t] = w;
    }
    __syncthreads();
    unsigned int wpref  = (wid > 0) ? wsum[wid - 1] : 0u;
    unsigned int t_excl = wpref + v - t_tot;
    unsigned int btot   = wsum[7];

    if (t == 0) {
        if (b > 0) {
            atomicExch(&g_part[b], (1ull << 32) | (unsigned long long)btot);
            unsigned int excl = 0;
            int pb = b - 1;
            while (true) {
                unsigned long long st = atomicAdd(&g_part[pb], 0ull);
                unsigned int status = (unsigned int)(st >> 32);
                if (status == 2u) { excl += (unsigned int)st; break; }
                if (status == 1u) { excl += (unsigned int)st; pb--; }
            }
            s_bpref = excl;
            atomicExch(&g_part[b], (2ull << 32) | (unsigned long long)(excl + btot));
        } else {
            s_bpref = 0u;
            atomicExch(&g_part[0], (2ull << 32) | (unsigned long long)btot);
        }
    }
    __syncthreads();
    unsigned int run = s_bpref + t_excl;
#pragma unroll
    for (int j = 0; j < 4; j++) {
        int i = base + j;
        if (i < NN) {
            g_rowptr[i] = (int)run;
            g_dis[i] = rsqrtf(1.0f + dl[j] * (1.0f / 8388608.0f));
        }
        run += c[j];
    }
    if (b == NSCANB - 1 && t == 255) g_rowptr[NN] = EE;
}

// ---------------- fill: no atomics ----------------
__global__ void k_fill(const int* __restrict__ src, const int* __restrict__ dst,
                       const float* __restrict__ ew) {
    int e = blockIdx.x * blockDim.x + threadIdx.x;
    if (e < EE) {
        int d = dst[e];
        int s = src[e];
        int p = g_rowptr[d] + g_pos[e];
        g_edge[p] = make_int2(s, __float_as_int(ew[e] * g_dis[s]));
    }
}

// ---------------- wf = W2 @ Wl, c = b2.Wl + bl ----------------
__global__ void k_wf(const float* __restrict__ W2, const float* __restrict__ b2,
                     const float* __restrict__ Wl, const float* __restrict__ bl) {
    __shared__ float sWl[H2];
    __shared__ float red[H2];
    int t = threadIdx.x;   // 128
    sWl[t] = Wl[t];
    __syncthreads();
    if (t < H1) {
        float s = 0.f;
#pragma unroll 8
        for (int m = 0; m < H2; m++) s += W2[t * H2 + m] * sWl[m];
        g_wf[t] = s;
    }
    red[t] = b2[t] * sWl[t];
    __syncthreads();
    if (t == 0) {
        float s = 0.f;
        for (int m = 0; m < H2; m++) s += red[m];
        g_c = s + bl[0];
    }
}

// ---------------- GEMM1 (tensor core): xh1 = fp16(x @ W1) ----------------
// 256 thr (8 warps), CTA tile 128 rows x 64 cols, warp tile 16x64.
// A: x tile fp32->fp16 smem [128][264] halfs; B: W1 fp16 [256][72] halfs.
#define A_STRIDE 264
#define B_STRIDE 72
#define G1_SMEM_BYTES (128 * A_STRIDE * 2 + FIN * B_STRIDE * 2)   // 104448
__global__ void __launch_bounds__(256, 2) k_gemm1(const float* __restrict__ x,
                                                  const float* __restrict__ W1) {
    extern __shared__ __half smh[];
    __half* sA = smh;                        // [128][A_STRIDE]
    __half* sB = smh + 128 * A_STRIDE;       // [256][B_STRIDE]
    const int t = threadIdx.x;
    const int lane = t & 31, warp = t >> 5;
    const int rb = blockIdx.x * 128;

    // ---- stage W1 fp32 -> fp16 smem [k][n]
    const float4* W4 = (const float4*)W1;    // 4096 float4
#pragma unroll
    for (int it = 0; it < 16; it++) {
        int idx = t + it * 256;
        int k = idx >> 4, n4 = idx & 15;
        float4 w = W4[idx];
        *(__half2*)&sB[k * B_STRIDE + n4 * 4 + 0] = __floats2half2_rn(w.x, w.y);
        *(__half2*)&sB[k * B_STRIDE + n4 * 4 + 2] = __floats2half2_rn(w.z, w.w);
    }

    // ---- stage x tile fp32 -> fp16 smem [row][k]
    const float4* X4 = (const float4*)x;     // 64 f4 per row
#pragma unroll
    for (int it = 0; it < 32; it++) {
        int idx = t + it * 256;              // 0..8191
        int row = idx >> 6, c4 = idx & 63;
        int grow = rb + row; if (grow >= NN) grow = NN - 1;
        float4 v = __ldg(&X4[(size_t)grow * 64 + c4]);
        *(__half2*)&sA[row * A_STRIDE + c4 * 4 + 0] = __floats2half2_rn(v.x, v.y);
        *(__half2*)&sA[row * A_STRIDE + c4 * 4 + 2] = __floats2half2_rn(v.z, v.w);
    }
    __syncthreads();

    // ---- per-lane ldmatrix addresses
    const int g = lane >> 3;                         // 0..3
    const int row_off = (lane & 7) + ((g & 1) << 3); // 0..15
    const int col_tile = g >> 1;                     // 0/1

    const int wr = warp * 16;
    unsigned int aBase;
    {
        const void* p = &sA[(wr + row_off) * A_STRIDE + col_tile * 8];
        asm("{ .reg .u64 tmp; cvta.to.shared.u64 tmp, %1; cvt.u32.u64 %0, tmp; }"
            : "=r"(aBase) : "l"(p));
    }
    unsigned int bBase;
    {
        const void* p = &sB[row_off * B_STRIDE + col_tile * 8];
        asm("{ .reg .u64 tmp; cvta.to.shared.u64 tmp, %1; cvt.u32.u64 %0, tmp; }"
            : "=r"(bBase) : "l"(p));
    }

    float acc[8][4];
#pragma unroll
    for (int n = 0; n < 8; n++)
#pragma unroll
        for (int c = 0; c < 4; c++) acc[n][c] = 0.f;

#pragma unroll 4
    for (int kc = 0; kc < FIN / 16; kc++) {          // 16 chunks
        unsigned int a0, a1, a2, a3;
        asm volatile("ldmatrix.sync.aligned.m8n8.x4.shared.b16 {%0,%1,%2,%3}, [%4];"
                     : "=r"(a0), "=r"(a1), "=r"(a2), "=r"(a3)
                     : "r"(aBase + kc * 32));        // 16 halfs = 32B
#pragma unroll
        for (int np = 0; np < 4; np++) {             // n-octet pairs
            unsigned int b0, b1, b2, b3;
            asm volatile("ldmatrix.sync.aligned.m8n8.x4.trans.shared.b16 {%0,%1,%2,%3}, [%4];"
                         : "=r"(b0), "=r"(b1), "=r"(b2), "=r"(b3)
                         : "r"(bBase + (kc * 16 * B_STRIDE + np * 16) * 2));
            asm volatile("mma.sync.aligned.m16n8k16.row.col.f32.f16.f16.f32 "
                         "{%0,%1,%2,%3},{%4,%5,%6,%7},{%8,%9},{%0,%1,%2,%3};"
                         : "+f"(acc[2 * np][0]), "+f"(acc[2 * np][1]),
                           "+f"(acc[2 * np][2]), "+f"(acc[2 * np][3])
                         : "r"(a0), "r"(a1), "r"(a2), "r"(a3), "r"(b0), "r"(b1));
            asm volatile("mma.sync.aligned.m16n8k16.row.col.f32.f16.f16.f32 "
                         "{%0,%1,%2,%3},{%4,%5,%6,%7},{%8,%9},{%0,%1,%2,%3};"
                         : "+f"(acc[2 * np + 1][0]), "+f"(acc[2 * np + 1][1]),
                           "+f"(acc[2 * np + 1][2]), "+f"(acc[2 * np + 1][3])
                         : "r"(a0), "r"(a1), "r"(a2), "r"(a3), "r"(b2), "r"(b3));
        }
    }

    // ---- epilogue: D fragments -> packed half2 stores
    const int gr = lane >> 2, gc = lane & 3;
#pragma unroll
    for (int n = 0; n < 8; n++) {
        int r0 = rb + wr + gr;
        int r1 = r0 + 8;
        __half2 d01 = __floats2half2_rn(acc[n][0], acc[n][1]);
        __half2 d23 = __floats2half2_rn(acc[n][2], acc[n][3]);
        if (r0 < NN) g_xh1[(size_t)r0 * 32 + n * 4 + gc] = d01;
        if (r1 < NN) g_xh1[(size_t)r1 * 32 + n * 4 + gc] = d23;
    }
}

// -------- agg1q: warp per node; fp16 rows --------
__global__ void k_agg1q(const float* __restrict__ b1) {
    int warp = (blockIdx.x * blockDim.x + threadIdx.x) >> 5;
    int lane = threadIdx.x & 31;
    if (warp >= NN) return;
    const int node = warp;
    int beg = g_rowptr[node], end = g_rowptr[node + 1];
    float2 v = make_float2(0.f, 0.f);
    const __half2* XH = g_xh1;

    int i = beg;
    if ((i & 1) && i < end) {
        int2 e = __ldg(&g_edge[i]);
        float w = __int_as_float(e.y);
        float2 a = __half22float2(__ldg(&XH[(size_t)e.x * 32 + lane]));
        v.x += w * a.x; v.y += w * a.y;
        i++;
    }
    for (; i + 1 < end; i += 2) {
        int4 ee = __ldg((const int4*)&g_edge[i]);
        float w0 = __int_as_float(ee.y), w1 = __int_as_float(ee.w);
        float2 a = __half22float2(__ldg(&XH[(size_t)ee.x * 32 + lane]));
        float2 b = __half22float2(__ldg(&XH[(size_t)ee.z * 32 + lane]));
        v.x += w0 * a.x + w1 * b.x;
        v.y += w0 * a.y + w1 * b.y;
    }
    if (i < end) {
        int2 e = __ldg(&g_edge[i]);
        float w = __int_as_float(e.y);
        float2 a = __half22float2(__ldg(&XH[(size_t)e.x * 32 + lane]));
        v.x += w * a.x; v.y += w * a.y;
    }

    float d = g_dis[node];
    float2 sv = __half22float2(XH[(size_t)node * 32 + lane]);
    float2 bb = __ldg(&((const float2*)b1)[lane]);
    float hx = fmaxf(fmaf(d, fmaf(d, sv.x, v.x), bb.x), 0.f);
    float hy = fmaxf(fmaf(d, fmaf(d, sv.y, v.y), bb.y), 0.f);
    float2 wf = ((const float2*)g_wf)[lane];
    float s = hx * wf.x + hy * wf.y;
#pragma unroll
    for (int o = 16; o > 0; o >>= 1) s += __shfl_down_sync(0xffffffffu, s, o);
    if (lane == 0) g_p[node] = s;
}

// ---------------- head ----------------
__global__ void k_head(const int* __restrict__ join, float* __restrict__ out) {
    int warp = (blockIdx.x * blockDim.x + threadIdx.x) >> 5;
    int lane = threadIdx.x & 31;
    if (warp >= BJ) return;
    int j = join[warp];
    int beg = g_rowptr[j], end = g_rowptr[j + 1];
    float acc = 0.f;
    for (int i = beg + lane; i < end; i += 32) {
        int2 e = __ldg(&g_edge[i]);
        acc += __int_as_float(e.y) * __ldg(&g_p[e.x]);
    }
#pragma unroll
    for (int o = 16; o > 0; o >>= 1) acc += __shfl_down_sync(0xffffffffu, acc, o);
    if (lane == 0) {
        float d = g_dis[j];
        float z = d * fmaf(d, g_p[j], acc) + g_c;
        out[warp] = 1.0f / (1.0f + expf(-z));
    }
}

// ---------------- launch ----------------
extern "C" void kernel_launch(void* const* d_in, const int* in_sizes, int n_in,
                              void* d_out, int out_size) {
    (void)in_sizes; (void)n_in; (void)out_size;
    const float* x    = (const float*)d_in[0];
    const int*   eidx = (const int*)  d_in[1];
    const int*   join = (const int*)  d_in[2];
    const float* ew   = (const float*)d_in[3];
    const float* W1   = (const float*)d_in[4];
    const float* b1   = (const float*)d_in[5];
    const float* W2   = (const float*)d_in[6];
    const float* b2   = (const float*)d_in[7];
    const float* Wl   = (const float*)d_in[8];
    const float* bl   = (const float*)d_in[9];
    float*       out  = (float*)d_out;

    const int* src = eidx;
    const int* dst = eidx + EE;

    static cudaStream_t sA = 0;
    static cudaEvent_t evRoot = 0, evA = 0;
    static bool inited = false;
    if (!inited) {
        cudaStreamCreateWithFlags(&sA, cudaStreamNonBlocking);
        cudaEventCreateWithFlags(&evRoot, cudaEventDisableTiming);
        cudaEventCreateWithFlags(&evA, cudaEventDisableTiming);
        cudaFuncSetAttribute(k_gemm1, cudaFuncAttributeMaxDynamicSharedMemorySize,
                             G1_SMEM_BYTES);
        inited = true;
    }

    const int g1_blocks = (NN + 127) / 128;           // 782

    cudaEventRecord(evRoot, 0);
    cudaStreamWaitEvent(sA, evRoot, 0);

    k_init  <<<(NN + 255) / 256, 256>>>();                         // #0 (B)
    k_hist  <<<EE / 256, 256>>>(dst, ew);                          // #1 (B)
    k_scan  <<<NSCANB, 256>>>();                                   // #2 (B)
    k_gemm1 <<<g1_blocks, 256, G1_SMEM_BYTES, sA>>>(x, W1);        // #3 (A) <- profiled
    k_wf    <<<1, 128, 0, sA>>>(W2, b2, Wl, bl);                   // #4 (A)
    k_fill  <<<EE / 256, 256>>>(src, dst, ew);                     // #5 (B)

    cudaEventRecord(evA, sA);
    cudaStreamWaitEvent(0, evA, 0);                                // join A -> B

    k_agg1q <<<(NN * 32 + 255) / 256, 256>>>(b1);                  // #6
    k_head  <<<(BJ * 32) / 256, 256>>>(join, out);                 // #7
}